// round 8
// baseline (speedup 1.0000x reference)
#include <cuda_runtime.h>
#include <math.h>
#include <stdint.h>

// ---------------- problem constants (fixed by setup_inputs) ----------------
#define T_TOK 32768
#define HID   384
#define NGATE 1536
#define NSEQ  16

// ---------------- scratch (static device arrays; no allocation) ------------
__device__ float g_X [(size_t)T_TOK * HID];    // [T,384] LSTM input (enc|prev)
__device__ float g_gx[(size_t)T_TOK * NGATE];  // [T,1536] input gate preacts
__device__ float g_y1[(size_t)T_TOK * HID];    // tanh(extra)@wh2^T
__device__ float g_x1[(size_t)T_TOK * HID];    // tanh(lstm)@wh1^T

__device__ __forceinline__ float sigm(float x) { return 1.f / (1.f + expf(-x)); }

// ============================================================================
// prepare: build X = [encoded | prev_label_embedding]
// ============================================================================
__global__ void prepare_kernel(const float* __restrict__ enc,
                               const int*   __restrict__ forced,
                               const int*   __restrict__ lens,
                               const float* __restrict__ emb,
                               const float* __restrict__ initt)
{
    int idx = blockIdx.x * blockDim.x + threadIdx.x;   // T*96 float4 slots
    if (idx >= T_TOK * 96) return;
    int tok = idx / 96;
    int q   = idx - tok * 96;

    float4 v;
    if (q < 64) {
        v = ((const float4*)enc)[(size_t)tok * 64 + q];
    } else {
        bool is64 = (lens[1] == 0);        // int64 layout heuristic (len!=0 always)
        bool is_start = false;
        int srt = 0;
        #pragma unroll
        for (int i = 0; i < NSEQ; i++) {
            if (tok == srt) is_start = true;
            srt += lens[is64 ? 2 * i : i];
        }
        if (is_start) {
            v = ((const float4*)initt)[q - 64];
        } else {
            int fi = forced[is64 ? 2 * (tok - 1) : (tok - 1)];
            v = ((const float4*)(emb + (size_t)fi * 128))[q - 64];
        }
    }
    ((float4*)g_X)[(size_t)tok * 96 + q] = v;
}

// ============================================================================
// SGEMM v2 (pipelined): C[M,N] = opA(A)[M,K] @ B[N,K]^T  (+bias/fusion)
// BM=BN=128, BK=16, 256 threads, 8x8 micro-tile.
// Register-prefetch + double-buffered smem: global loads for tile k+1 are
// issued before computing tile k; ONE __syncthreads per iteration.
// ============================================================================
#define BM 128
#define BN 128
#define BK 16

#define MODE_BIAS   0
#define MODE_TANHA  1
#define MODE_FUSION 2

__device__ __forceinline__ float fuse_elem(float pre, float L, float Ev)
{
    float f  = 1.f / (1.f + expf(-pre));
    float x0 = tanhf(L);
    float y0 = tanhf(Ev);
    float x2 = f * x0 + L;
    float y2 = (1.f - f) * y0 + Ev;
    return f * x2 + (1.f - f) * y2;
}

template<int MODE>
__global__ __launch_bounds__(256)
void sgemm_k(const float* __restrict__ A, const float* __restrict__ A2,
             const float* __restrict__ B, const float* __restrict__ bias,
             float* __restrict__ C,
             const float* __restrict__ E1, const float* __restrict__ E2,
             int N, int K)
{
    __shared__ float As[2][BK][BM + 4];
    __shared__ float Bs[2][BK][BN + 4];

    int tid = threadIdx.x;
    int m0  = blockIdx.y * BM;
    int n0  = blockIdx.x * BN;
    int tx  = tid & 15;
    int ty  = tid >> 4;

    // each thread loads float4 elements tid and tid+256 of the 512-float4 tile
    int rA0 = tid >> 2;            // rows 0..63
    int rA1 = (tid + 256) >> 2;    // rows 64..127
    int kq  = tid & 3;             // same k-quad for both halves

    float acc[8][8];
    #pragma unroll
    for (int i = 0; i < 8; i++)
        #pragma unroll
        for (int j = 0; j < 8; j++) acc[i][j] = 0.f;

    float4 pA0, pA1, pB0, pB1;

#define FETCH_TILE(k0_)                                                        \
    do {                                                                       \
        int _k0 = (k0_);                                                       \
        const float *sA0, *sA1;                                                \
        if (MODE == MODE_FUSION) {                                             \
            if (_k0 < 384) {                                                   \
                sA0 = A + (size_t)(m0 + rA0) * 384 + _k0;                      \
                sA1 = A + (size_t)(m0 + rA1) * 384 + _k0;                      \
            } else {                                                           \
                sA0 = A2 + (size_t)(m0 + rA0) * 384 + (_k0 - 384);             \
                sA1 = A2 + (size_t)(m0 + rA1) * 384 + (_k0 - 384);             \
            }                                                                  \
        } else {                                                               \
            sA0 = A + (size_t)(m0 + rA0) * K + _k0;                            \
            sA1 = A + (size_t)(m0 + rA1) * K + _k0;                            \
        }                                                                      \
        pA0 = *(const float4*)(sA0 + kq * 4);                                  \
        pA1 = *(const float4*)(sA1 + kq * 4);                                  \
        pB0 = *(const float4*)(B + (size_t)(n0 + rA0) * K + _k0 + kq * 4);     \
        pB1 = *(const float4*)(B + (size_t)(n0 + rA1) * K + _k0 + kq * 4);     \
    } while (0)

#define STORE_TILE(buf_)                                                       \
    do {                                                                       \
        int _b = (buf_);                                                       \
        float4 vA0 = pA0, vA1 = pA1;                                           \
        if (MODE == MODE_TANHA) {                                              \
            vA0.x = tanhf(vA0.x); vA0.y = tanhf(vA0.y);                        \
            vA0.z = tanhf(vA0.z); vA0.w = tanhf(vA0.w);                        \
            vA1.x = tanhf(vA1.x); vA1.y = tanhf(vA1.y);                        \
            vA1.z = tanhf(vA1.z); vA1.w = tanhf(vA1.w);                        \
        }                                                                      \
        As[_b][kq * 4 + 0][rA0] = vA0.x; As[_b][kq * 4 + 1][rA0] = vA0.y;      \
        As[_b][kq * 4 + 2][rA0] = vA0.z; As[_b][kq * 4 + 3][rA0] = vA0.w;      \
        As[_b][kq * 4 + 0][rA1] = vA1.x; As[_b][kq * 4 + 1][rA1] = vA1.y;      \
        As[_b][kq * 4 + 2][rA1] = vA1.z; As[_b][kq * 4 + 3][rA1] = vA1.w;      \
        Bs[_b][kq * 4 + 0][rA0] = pB0.x; Bs[_b][kq * 4 + 1][rA0] = pB0.y;      \
        Bs[_b][kq * 4 + 2][rA0] = pB0.z; Bs[_b][kq * 4 + 3][rA0] = pB0.w;      \
        Bs[_b][kq * 4 + 0][rA1] = pB1.x; Bs[_b][kq * 4 + 1][rA1] = pB1.y;      \
        Bs[_b][kq * 4 + 2][rA1] = pB1.z; Bs[_b][kq * 4 + 3][rA1] = pB1.w;      \
    } while (0)

    FETCH_TILE(0);
    STORE_TILE(0);
    __syncthreads();

    int nIter = K / BK;
    for (int it = 0; it < nIter; it++) {
        int cur = it & 1;
        if (it + 1 < nIter) FETCH_TILE((it + 1) * BK);   // global loads in flight

        #pragma unroll
        for (int kk = 0; kk < BK; kk++) {
            float a[8], b[8];
            float4 a0 = *(const float4*)&As[cur][kk][ty * 8];
            float4 a1 = *(const float4*)&As[cur][kk][ty * 8 + 4];
            float4 b0 = *(const float4*)&Bs[cur][kk][tx * 8];
            float4 b1 = *(const float4*)&Bs[cur][kk][tx * 8 + 4];
            a[0]=a0.x; a[1]=a0.y; a[2]=a0.z; a[3]=a0.w;
            a[4]=a1.x; a[5]=a1.y; a[6]=a1.z; a[7]=a1.w;
            b[0]=b0.x; b[1]=b0.y; b[2]=b0.z; b[3]=b0.w;
            b[4]=b1.x; b[5]=b1.y; b[6]=b1.z; b[7]=b1.w;
            #pragma unroll
            for (int i = 0; i < 8; i++)
                #pragma unroll
                for (int j = 0; j < 8; j++)
                    acc[i][j] = fmaf(a[i], b[j], acc[i][j]);
        }

        if (it + 1 < nIter) STORE_TILE(cur ^ 1);         // fill other buffer
        __syncthreads();
    }

#undef FETCH_TILE
#undef STORE_TILE

    // ---- epilogue ----
    #pragma unroll
    for (int i = 0; i < 8; i++) {
        size_t m = (size_t)(m0 + ty * 8 + i);
        #pragma unroll
        for (int q = 0; q < 2; q++) {
            int n = n0 + tx * 8 + q * 4;
            float r0 = acc[i][q * 4 + 0], r1 = acc[i][q * 4 + 1];
            float r2 = acc[i][q * 4 + 2], r3 = acc[i][q * 4 + 3];
            if (MODE == MODE_BIAS) {
                float4 bv = *(const float4*)(bias + n);
                r0 += bv.x; r1 += bv.y; r2 += bv.z; r3 += bv.w;
            }
            if (MODE == MODE_FUSION) {
                float4 L = *(const float4*)(E1 + m * 384 + n);
                float4 E = *(const float4*)(E2 + m * 384 + n);
                r0 = fuse_elem(r0, L.x, E.x); r1 = fuse_elem(r1, L.y, E.y);
                r2 = fuse_elem(r2, L.z, E.z); r3 = fuse_elem(r3, L.w, E.w);
            }
            float4 ov = make_float4(r0, r1, r2, r3);
            *(float4*)(C + m * N + n) = ov;
        }
    }
}

// ============================================================================
// LSTM scan v3 (VERBATIM from the Round-4 PASSING source, 8913.6us):
// 16 sequences x 8-CTA clusters, 384 thr/CTA.
// Thread (ks=t&7, rb=t>>3): all 4 gate rows of unit rb, k-slice ks*48..+48.
// ============================================================================
#define SCAN_THREADS 384
#define WS_FLOATS (24 * 384 * 4)     // 96 floats/thread of W in smem
#define HPAD 416                     // 8 chunks * 52 floats
#define MBAR_OFF ((WS_FLOATS + 2 * HPAD) * 4)
#define SCAN_SMEM_BYTES (MBAR_OFF + 64)

#define SCAN_MBAR_INIT(addr, cnt) \
    asm volatile("mbarrier.init.shared.b64 [%0], %1;" :: "r"(addr), "r"(cnt) : "memory")
#define SCAN_EXPECT_TX(addr, tx) \
    asm volatile("mbarrier.arrive.expect_tx.shared.b64 _, [%0], %1;" :: "r"(addr), "r"(tx) : "memory")
#define SCAN_ARRIVE_REMOTE(addr) \
    asm volatile("mbarrier.arrive.shared::cluster.b64 _, [%0];" :: "r"(addr) : "memory")
#define SCAN_ST_ASYNC(addr, val, mbar) \
    asm volatile("st.async.weak.shared::cluster.mbarrier::complete_tx::bytes.b32 [%0], %1, [%2];" \
                 :: "r"(addr), "r"(val), "r"(mbar) : "memory")
#define SCAN_WAIT(mbar, parity) do {                                           \
    uint32_t _done;                                                            \
    asm volatile("{\n\t.reg .pred p;\n\t"                                      \
      "mbarrier.try_wait.parity.acquire.cluster.shared::cta.b64 p, [%1], %2;\n\t" \
      "selp.b32 %0, 1, 0, p;\n\t}" : "=r"(_done) : "r"(mbar), "r"(parity) : "memory"); \
    while (!_done) {                                                           \
      asm volatile("{\n\t.reg .pred p;\n\t"                                    \
        "mbarrier.try_wait.parity.acquire.cluster.shared::cta.b64 p, [%1], %2, 0x989680;\n\t" \
        "selp.b32 %0, 1, 0, p;\n\t}" : "=r"(_done) : "r"(mbar), "r"(parity) : "memory"); \
    }                                                                          \
} while (0)

__global__ void __cluster_dims__(8, 1, 1) __launch_bounds__(SCAN_THREADS, 1)
lstm_scan_kernel(const float* __restrict__ gx, const float* __restrict__ W_hh,
                 const float* __restrict__ b_hh, const int* __restrict__ lens,
                 float* __restrict__ lstm)
{
    extern __shared__ float sm[];
    float4* Ws4   = (float4*)sm;          // [24][384] float4 (gates g,o)
    float*  h_pad = sm + WS_FLOATS;       // [2][HPAD]

    uint32_t smem_base;
    asm("{ .reg .u64 u; cvta.to.shared.u64 u, %1; cvt.u32.u64 %0, u; }"
        : "=r"(smem_base) : "l"(sm));
    uint32_t hpad_base = smem_base + WS_FLOATS * 4;
    uint32_t mbar_base = smem_base + MBAR_OFF;   // full0@0 full1@8 empty0@16 empty1@24

    int t = threadIdx.x;
    uint32_t rank;
    asm("mov.u32 %0, %%cluster_ctarank;" : "=r"(rank));
    int seq = blockIdx.x >> 3;

    bool is64 = (lens[1] == 0);
    int start = 0;
    for (int i = 0; i < seq; i++) start += lens[is64 ? 2 * i : i];
    int len = lens[is64 ? 2 * seq : seq];

    int ks    = t & 7;        // k-slice: k in [ks*48, ks*48+48)
    int rb    = t >> 3;       // hidden unit (local 0..47)
    int kbase = ks * 48;
    bool owner = (ks == 0);

    // ---- stage W: gates i,f (rows) -> registers; gates g,o -> smem ----
    float4 wi[12], wf[12];
    #pragma unroll
    for (int g = 0; g < 4; g++) {
        int grow = g * HID + (int)rank * 48 + rb;
        const float4* src = (const float4*)(W_hh + (size_t)grow * HID + kbase);
        if (g == 0) {
            #pragma unroll
            for (int j = 0; j < 12; j++) wi[j] = src[j];
        } else if (g == 1) {
            #pragma unroll
            for (int j = 0; j < 12; j++) wf[j] = src[j];
        } else {
            #pragma unroll
            for (int j = 0; j < 12; j++) Ws4[((g - 2) * 12 + j) * 384 + t] = src[j];
        }
    }

    // ---- owner-lane state ----
    float c = 0.f, bh0 = 0.f, bh1 = 0.f, bh2 = 0.f, bh3 = 0.f;
    const float* gxp  = gx;
    float*       lout = lstm;
    if (owner) {
        int u = (int)rank * 48 + rb;
        bh0 = b_hh[u];            bh1 = b_hh[HID + u];
        bh2 = b_hh[2 * HID + u];  bh3 = b_hh[3 * HID + u];
        gxp  = gx   + (size_t)start * NGATE + u;
        lout = lstm + (size_t)start * HID   + u;
    }

    // ---- peer base addresses (h_pad and mbar block in each cluster CTA) ----
    uint32_t peer_h[8], peer_m[8];
    #pragma unroll
    for (int r = 0; r < 8; r++) {
        asm("mapa.shared::cluster.u32 %0, %1, %2;" : "=r"(peer_h[r]) : "r"(hpad_base), "r"(r));
        asm("mapa.shared::cluster.u32 %0, %1, %2;" : "=r"(peer_m[r]) : "r"(mbar_base), "r"(r));
    }

    // ---- init: mbars + zero h buffers, publish to cluster ----
    if (t == 0) {
        SCAN_MBAR_INIT(mbar_base + 0, 1);    // full0 (tx-based)
        SCAN_MBAR_INIT(mbar_base + 8, 1);    // full1
        SCAN_MBAR_INIT(mbar_base + 16, 8);   // empty0 (8 CTA arrives)
        SCAN_MBAR_INIT(mbar_base + 24, 8);   // empty1
        SCAN_EXPECT_TX(mbar_base + 0, 1536); // pre-arm phase 0 of both fulls
        SCAN_EXPECT_TX(mbar_base + 8, 1536);
    }
    for (int i = t; i < 2 * HPAD; i += SCAN_THREADS) h_pad[i] = 0.f;
    __syncthreads();
    asm volatile("barrier.cluster.arrive.aligned;" ::: "memory");
    asm volatile("barrier.cluster.wait.aligned;" ::: "memory");

    int phF0 = 0, phF1 = 0, phE0 = 0, phE1 = 0;

    for (int step = 0; step < len; step++) {
        // gx for this step (owner lanes) — issue before any waiting
        float g0 = 0.f, g1 = 0.f, g2 = 0.f, g3 = 0.f;
        if (owner) {
            const float* gp = gxp + (size_t)step * NGATE;
            g0 = __ldg(gp);
            g1 = __ldg(gp + HID);
            g2 = __ldg(gp + 2 * HID);
            g3 = __ldg(gp + 3 * HID);
        }
        // all local threads done with previous step (incl. reads of old buffer)
        __syncthreads();

        if (step > 0) {
            // t0: tell all peers the buffer we read last step is free again
            if (t == 0) {
                int eb = (step - 1) & 1;
                #pragma unroll
                for (int r = 0; r < 8; r++)
                    SCAN_ARRIVE_REMOTE(peer_m[r] + 16 + eb * 8);
            }
            // wait for this step's h (full barrier of buffer step&1)
            int b = step & 1;
            if (b) { SCAN_WAIT(mbar_base + 8, phF1); phF1 ^= 1; }
            else   { SCAN_WAIT(mbar_base + 0, phF0); phF0 ^= 1; }
        }

        // ---- dot: 4 gate rows of unit rb over 48 k-elems ----
        int par = step & 1;
        const float4* h4 = (const float4*)(h_pad + par * HPAD + ks * 52);
        float a0 = 0.f, a1 = 0.f, a2 = 0.f, a3 = 0.f;
        #pragma unroll
        for (int j = 0; j < 12; j++) {
            float4 hv = h4[j];
            float4 v0 = wi[j];
            float4 v1 = wf[j];
            float4 v2 = Ws4[j * 384 + t];
            float4 v3 = Ws4[(12 + j) * 384 + t];
            a0 = fmaf(v0.x, hv.x, a0); a0 = fmaf(v0.y, hv.y, a0);
            a0 = fmaf(v0.z, hv.z, a0); a0 = fmaf(v0.w, hv.w, a0);
            a1 = fmaf(v1.x, hv.x, a1); a1 = fmaf(v1.y, hv.y, a1);
            a1 = fmaf(v1.z, hv.z, a1); a1 = fmaf(v1.w, hv.w, a1);
            a2 = fmaf(v2.x, hv.x, a2); a2 = fmaf(v2.y, hv.y, a2);
            a2 = fmaf(v2.z, hv.z, a2); a2 = fmaf(v2.w, hv.w, a2);
            a3 = fmaf(v3.x, hv.x, a3); a3 = fmaf(v3.y, hv.y, a3);
            a3 = fmaf(v3.z, hv.z, a3); a3 = fmaf(v3.w, hv.w, a3);
        }
        // reduce over the 8 k-slices (lane bits 0..2)
        a0 += __shfl_xor_sync(0xffffffffu, a0, 1);
        a1 += __shfl_xor_sync(0xffffffffu, a1, 1);
        a2 += __shfl_xor_sync(0xffffffffu, a2, 1);
        a3 += __shfl_xor_sync(0xffffffffu, a3, 1);
        a0 += __shfl_xor_sync(0xffffffffu, a0, 2);
        a1 += __shfl_xor_sync(0xffffffffu, a1, 2);
        a2 += __shfl_xor_sync(0xffffffffu, a2, 2);
        a3 += __shfl_xor_sync(0xffffffffu, a3, 2);
        a0 += __shfl_xor_sync(0xffffffffu, a0, 4);
        a1 += __shfl_xor_sync(0xffffffffu, a1, 4);
        a2 += __shfl_xor_sync(0xffffffffu, a2, 4);
        a3 += __shfl_xor_sync(0xffffffffu, a3, 4);

        if (owner) {
            float gi = a0 + g0 + bh0;
            float gf = a1 + g1 + bh1;
            float gg = a2 + g2 + bh2;
            float go = a3 + g3 + bh3;
            c = sigm(gf) * c + sigm(gi) * tanhf(gg);
            float h = sigm(go) * tanhf(c);
            lout[(size_t)step * HID] = h;

            if (step < len - 1) {
                int bw = (step + 1) & 1;
                // wait until every CTA finished reading buffer bw (step-1 dot)
                if (step >= 1) {
                    if (bw) { SCAN_WAIT(mbar_base + 24, phE1); phE1 ^= 1; }
                    else    { SCAN_WAIT(mbar_base + 16, phE0); phE0 ^= 1; }
                }
                // t0 re-arms the full barrier just consumed (next use = step+2)
                // BEFORE its own sends: remote senders to it causally depend on
                // t0's bytes below, so expect_tx precedes every complete_tx.
                if (t == 0 && step >= 1 && step <= len - 3)
                    SCAN_EXPECT_TX(mbar_base + (step & 1) * 8, 1536);
                // push h to all 8 CTAs' buffer bw with tx accounting
                uint32_t off = (uint32_t)(bw * HPAD + (int)rank * 52 + rb) * 4;
                uint32_t hb  = __float_as_uint(h);
                #pragma unroll
                for (int r = 0; r < 8; r++)
                    SCAN_ST_ASYNC(peer_h[r] + off, hb, peer_m[r] + bw * 8);
            }
        }
    }

    asm volatile("barrier.cluster.arrive.aligned;" ::: "memory");
    asm volatile("barrier.cluster.wait.aligned;" ::: "memory");
}

// ============================================================================
// launch
// ============================================================================
extern "C" void kernel_launch(void* const* d_in, const int* in_sizes, int n_in,
                              void* d_out, int out_size)
{
    const float* enc    = (const float*)d_in[0];
    const float* extra  = (const float*)d_in[1];
    const int*   forced = (const int*)  d_in[2];
    const int*   lens   = (const int*)  d_in[3];
    const float* emb    = (const float*)d_in[4];
    const float* initt  = (const float*)d_in[5];
    const float* W_ih   = (const float*)d_in[6];
    const float* W_hh   = (const float*)d_in[7];
    const float* b_ih   = (const float*)d_in[8];
    const float* b_hh   = (const float*)d_in[9];
    const float* wh1    = (const float*)d_in[10];
    const float* wh2    = (const float*)d_in[11];
    const float* wsig   = (const float*)d_in[12];

    float* out    = (float*)d_out;
    float* fusion = out;                               // [T,384]
    float* lstm   = out + (size_t)T_TOK * HID;         // [T,384]

    float *Xp, *gxp, *y1p, *x1p;
    cudaGetSymbolAddress((void**)&Xp,  g_X);
    cudaGetSymbolAddress((void**)&gxp, g_gx);
    cudaGetSymbolAddress((void**)&y1p, g_y1);
    cudaGetSymbolAddress((void**)&x1p, g_x1);

    cudaFuncSetAttribute(lstm_scan_kernel,
                         cudaFuncAttributeMaxDynamicSharedMemorySize,
                         SCAN_SMEM_BYTES);

    // 1) build X
    prepare_kernel<<<(T_TOK * 96 + 255) / 256, 256>>>(enc, forced, lens, emb, initt);

    // 2) gx = X @ W_ih^T + b_ih   [T,1536]
    sgemm_k<MODE_BIAS><<<dim3(NGATE / BN, T_TOK / BM), 256>>>(
        Xp, nullptr, W_ih, b_ih, gxp, nullptr, nullptr, NGATE, HID);

    // 3) LSTM scan -> lstm (second half of d_out)
    lstm_scan_kernel<<<128, SCAN_THREADS, SCAN_SMEM_BYTES>>>(gxp, W_hh, b_hh, lens, lstm);

    // 4) y1 = tanh(extra) @ wh2^T
    sgemm_k<MODE_TANHA><<<dim3(HID / BN, T_TOK / BM), 256>>>(
        extra, nullptr, wh2, nullptr, y1p, nullptr, nullptr, HID, HID);

    // 5) x1 = tanh(lstm) @ wh1^T
    sgemm_k<MODE_TANHA><<<dim3(HID / BN, T_TOK / BM), 256>>>(
        lstm, nullptr, wh1, nullptr, x1p, nullptr, nullptr, HID, HID);

    // 6) f = sigmoid([x1|y1] @ Wsig^T); fusion epilogue -> first half of d_out
    sgemm_k<MODE_FUSION><<<dim3(HID / BN, T_TOK / BM), 256>>>(
        x1p, y1p, wsig, nullptr, fusion, lstm, extra, HID, 2 * HID);
}

// round 11
// speedup vs baseline: 1.0088x; 1.0088x over previous
#include <cuda_runtime.h>
#include <math.h>
#include <stdint.h>

// ---------------- problem constants (fixed by setup_inputs) ----------------
#define T_TOK 32768
#define HID   384
#define NGATE 1536
#define NSEQ  16

// ---------------- scratch (static device arrays; no allocation) ------------
__device__ float g_X [(size_t)T_TOK * HID];    // [T,384] LSTM input (enc|prev)
__device__ float g_gx[(size_t)T_TOK * NGATE];  // [T,1536] input gate preacts
__device__ float g_y1[(size_t)T_TOK * HID];    // tanh(extra)@wh2^T
__device__ float g_x1[(size_t)T_TOK * HID];    // tanh(lstm)@wh1^T

__device__ __forceinline__ float sigm(float x) { return 1.f / (1.f + expf(-x)); }

// ============================================================================
// prepare: build X = [encoded | prev_label_embedding]
// ============================================================================
__global__ void prepare_kernel(const float* __restrict__ enc,
                               const int*   __restrict__ forced,
                               const int*   __restrict__ lens,
                               const float* __restrict__ emb,
                               const float* __restrict__ initt)
{
    int idx = blockIdx.x * blockDim.x + threadIdx.x;   // T*96 float4 slots
    if (idx >= T_TOK * 96) return;
    int tok = idx / 96;
    int q   = idx - tok * 96;

    float4 v;
    if (q < 64) {
        v = ((const float4*)enc)[(size_t)tok * 64 + q];
    } else {
        bool is64 = (lens[1] == 0);        // int64 layout heuristic (len!=0 always)
        bool is_start = false;
        int srt = 0;
        #pragma unroll
        for (int i = 0; i < NSEQ; i++) {
            if (tok == srt) is_start = true;
            srt += lens[is64 ? 2 * i : i];
        }
        if (is_start) {
            v = ((const float4*)initt)[q - 64];
        } else {
            int fi = forced[is64 ? 2 * (tok - 1) : (tok - 1)];
            v = ((const float4*)(emb + (size_t)fi * 128))[q - 64];
        }
    }
    ((float4*)g_X)[(size_t)tok * 96 + q] = v;
}

// ============================================================================
// SGEMM (PROVEN R2 version): C = opA(A) @ B^T (+epilogue)
// BM=BN=128, BK=16, 256 threads, 8x8 micro-tile.
// ============================================================================
#define BM 128
#define BN 128
#define BK 16

#define MODE_BIAS   0
#define MODE_TANHA  1
#define MODE_FUSION 2

__device__ __forceinline__ float fuse_elem(float pre, float L, float Ev)
{
    float f  = 1.f / (1.f + expf(-pre));
    float x0 = tanhf(L);
    float y0 = tanhf(Ev);
    float x2 = f * x0 + L;
    float y2 = (1.f - f) * y0 + Ev;
    return f * x2 + (1.f - f) * y2;
}

template<int MODE>
__global__ __launch_bounds__(256)
void sgemm_k(const float* __restrict__ A, const float* __restrict__ A2,
             const float* __restrict__ B, const float* __restrict__ bias,
             float* __restrict__ C,
             const float* __restrict__ E1, const float* __restrict__ E2,
             int N, int K)
{
    __shared__ float As[BK][BM + 4];
    __shared__ float Bs[BK][BN + 4];

    int tid = threadIdx.x;
    int m0  = blockIdx.y * BM;
    int n0  = blockIdx.x * BN;
    int tx  = tid & 15;
    int ty  = tid >> 4;

    float acc[8][8];
    #pragma unroll
    for (int i = 0; i < 8; i++)
        #pragma unroll
        for (int j = 0; j < 8; j++) acc[i][j] = 0.f;

    for (int k0 = 0; k0 < K; k0 += BK) {
        #pragma unroll
        for (int i = 0; i < 2; i++) {
            int f  = tid + i * 256;
            int r  = f >> 2;
            int kq = f & 3;
            const float* src;
            if (MODE == MODE_FUSION) {
                src = (k0 < 384) ? (A  + (size_t)(m0 + r) * 384 + k0)
                                 : (A2 + (size_t)(m0 + r) * 384 + (k0 - 384));
            } else {
                src = A + (size_t)(m0 + r) * K + k0;
            }
            float4 v = *(const float4*)(src + kq * 4);
            if (MODE == MODE_TANHA) {
                v.x = tanhf(v.x); v.y = tanhf(v.y);
                v.z = tanhf(v.z); v.w = tanhf(v.w);
            }
            As[kq * 4 + 0][r] = v.x; As[kq * 4 + 1][r] = v.y;
            As[kq * 4 + 2][r] = v.z; As[kq * 4 + 3][r] = v.w;
        }
        #pragma unroll
        for (int i = 0; i < 2; i++) {
            int f  = tid + i * 256;
            int r  = f >> 2;
            int kq = f & 3;
            float4 v = *(const float4*)(B + (size_t)(n0 + r) * K + k0 + kq * 4);
            Bs[kq * 4 + 0][r] = v.x; Bs[kq * 4 + 1][r] = v.y;
            Bs[kq * 4 + 2][r] = v.z; Bs[kq * 4 + 3][r] = v.w;
        }
        __syncthreads();

        #pragma unroll
        for (int kk = 0; kk < BK; kk++) {
            float a[8], b[8];
            float4 a0 = *(const float4*)&As[kk][ty * 8];
            float4 a1 = *(const float4*)&As[kk][ty * 8 + 4];
            float4 b0 = *(const float4*)&Bs[kk][tx * 8];
            float4 b1 = *(const float4*)&Bs[kk][tx * 8 + 4];
            a[0]=a0.x; a[1]=a0.y; a[2]=a0.z; a[3]=a0.w;
            a[4]=a1.x; a[5]=a1.y; a[6]=a1.z; a[7]=a1.w;
            b[0]=b0.x; b[1]=b0.y; b[2]=b0.z; b[3]=b0.w;
            b[4]=b1.x; b[5]=b1.y; b[6]=b1.z; b[7]=b1.w;
            #pragma unroll
            for (int i = 0; i < 8; i++)
                #pragma unroll
                for (int j = 0; j < 8; j++)
                    acc[i][j] = fmaf(a[i], b[j], acc[i][j]);
        }
        __syncthreads();
    }

    #pragma unroll
    for (int i = 0; i < 8; i++) {
        size_t m = (size_t)(m0 + ty * 8 + i);
        #pragma unroll
        for (int q = 0; q < 2; q++) {
            int n = n0 + tx * 8 + q * 4;
            float r0 = acc[i][q * 4 + 0], r1 = acc[i][q * 4 + 1];
            float r2 = acc[i][q * 4 + 2], r3 = acc[i][q * 4 + 3];
            if (MODE == MODE_BIAS) {
                float4 bv = *(const float4*)(bias + n);
                r0 += bv.x; r1 += bv.y; r2 += bv.z; r3 += bv.w;
            }
            if (MODE == MODE_FUSION) {
                float4 L = *(const float4*)(E1 + m * 384 + n);
                float4 E = *(const float4*)(E2 + m * 384 + n);
                r0 = fuse_elem(r0, L.x, E.x); r1 = fuse_elem(r1, L.y, E.y);
                r2 = fuse_elem(r2, L.z, E.z); r3 = fuse_elem(r3, L.w, E.w);
            }
            float4 ov = make_float4(r0, r1, r2, r3);
            *(float4*)(C + m * N + n) = ov;
        }
    }
}

// ============================================================================
// LSTM scan v3 (VERBATIM from the Round-4 PASSING source, 8913.6us):
// 16 sequences x 8-CTA clusters, 384 thr/CTA.
// Thread (ks=t&7, rb=t>>3): all 4 gate rows of unit rb, k-slice ks*48..+48.
// ============================================================================
#define SCAN_THREADS 384
#define WS_FLOATS (24 * 384 * 4)     // 96 floats/thread of W in smem
#define HPAD 416                     // 8 chunks * 52 floats
#define MBAR_OFF ((WS_FLOATS + 2 * HPAD) * 4)
#define SCAN_SMEM_BYTES (MBAR_OFF + 64)

#define SCAN_MBAR_INIT(addr, cnt) \
    asm volatile("mbarrier.init.shared.b64 [%0], %1;" :: "r"(addr), "r"(cnt) : "memory")
#define SCAN_EXPECT_TX(addr, tx) \
    asm volatile("mbarrier.arrive.expect_tx.shared.b64 _, [%0], %1;" :: "r"(addr), "r"(tx) : "memory")
#define SCAN_ARRIVE_REMOTE(addr) \
    asm volatile("mbarrier.arrive.shared::cluster.b64 _, [%0];" :: "r"(addr) : "memory")
#define SCAN_ST_ASYNC(addr, val, mbar) \
    asm volatile("st.async.weak.shared::cluster.mbarrier::complete_tx::bytes.b32 [%0], %1, [%2];" \
                 :: "r"(addr), "r"(val), "r"(mbar) : "memory")
#define SCAN_WAIT(mbar, parity) do {                                           \
    uint32_t _done;                                                            \
    asm volatile("{\n\t.reg .pred p;\n\t"                                      \
      "mbarrier.try_wait.parity.acquire.cluster.shared::cta.b64 p, [%1], %2;\n\t" \
      "selp.b32 %0, 1, 0, p;\n\t}" : "=r"(_done) : "r"(mbar), "r"(parity) : "memory"); \
    while (!_done) {                                                           \
      asm volatile("{\n\t.reg .pred p;\n\t"                                    \
        "mbarrier.try_wait.parity.acquire.cluster.shared::cta.b64 p, [%1], %2, 0x989680;\n\t" \
        "selp.b32 %0, 1, 0, p;\n\t}" : "=r"(_done) : "r"(mbar), "r"(parity) : "memory"); \
    }                                                                          \
} while (0)

__global__ void __cluster_dims__(8, 1, 1) __launch_bounds__(SCAN_THREADS, 1)
lstm_scan_kernel(const float* __restrict__ gx, const float* __restrict__ W_hh,
                 const float* __restrict__ b_hh, const int* __restrict__ lens,
                 float* __restrict__ lstm)
{
    extern __shared__ float sm[];
    float4* Ws4   = (float4*)sm;          // [24][384] float4 (gates g,o)
    float*  h_pad = sm + WS_FLOATS;       // [2][HPAD]

    uint32_t smem_base;
    asm("{ .reg .u64 u; cvta.to.shared.u64 u, %1; cvt.u32.u64 %0, u; }"
        : "=r"(smem_base) : "l"(sm));
    uint32_t hpad_base = smem_base + WS_FLOATS * 4;
    uint32_t mbar_base = smem_base + MBAR_OFF;   // full0@0 full1@8 empty0@16 empty1@24

    int t = threadIdx.x;
    uint32_t rank;
    asm("mov.u32 %0, %%cluster_ctarank;" : "=r"(rank));
    int seq = blockIdx.x >> 3;

    bool is64 = (lens[1] == 0);
    int start = 0;
    for (int i = 0; i < seq; i++) start += lens[is64 ? 2 * i : i];
    int len = lens[is64 ? 2 * seq : seq];

    int ks    = t & 7;        // k-slice: k in [ks*48, ks*48+48)
    int rb    = t >> 3;       // hidden unit (local 0..47)
    int kbase = ks * 48;
    bool owner = (ks == 0);

    // ---- stage W: gates i,f (rows) -> registers; gates g,o -> smem ----
    float4 wi[12], wf[12];
    #pragma unroll
    for (int g = 0; g < 4; g++) {
        int grow = g * HID + (int)rank * 48 + rb;
        const float4* src = (const float4*)(W_hh + (size_t)grow * HID + kbase);
        if (g == 0) {
            #pragma unroll
            for (int j = 0; j < 12; j++) wi[j] = src[j];
        } else if (g == 1) {
            #pragma unroll
            for (int j = 0; j < 12; j++) wf[j] = src[j];
        } else {
            #pragma unroll
            for (int j = 0; j < 12; j++) Ws4[((g - 2) * 12 + j) * 384 + t] = src[j];
        }
    }

    // ---- owner-lane state ----
    float c = 0.f, bh0 = 0.f, bh1 = 0.f, bh2 = 0.f, bh3 = 0.f;
    const float* gxp  = gx;
    float*       lout = lstm;
    if (owner) {
        int u = (int)rank * 48 + rb;
        bh0 = b_hh[u];            bh1 = b_hh[HID + u];
        bh2 = b_hh[2 * HID + u];  bh3 = b_hh[3 * HID + u];
        gxp  = gx   + (size_t)start * NGATE + u;
        lout = lstm + (size_t)start * HID   + u;
    }

    // ---- peer base addresses (h_pad and mbar block in each cluster CTA) ----
    uint32_t peer_h[8], peer_m[8];
    #pragma unroll
    for (int r = 0; r < 8; r++) {
        asm("mapa.shared::cluster.u32 %0, %1, %2;" : "=r"(peer_h[r]) : "r"(hpad_base), "r"(r));
        asm("mapa.shared::cluster.u32 %0, %1, %2;" : "=r"(peer_m[r]) : "r"(mbar_base), "r"(r));
    }

    // ---- init: mbars + zero h buffers, publish to cluster ----
    if (t == 0) {
        SCAN_MBAR_INIT(mbar_base + 0, 1);    // full0 (tx-based)
        SCAN_MBAR_INIT(mbar_base + 8, 1);    // full1
        SCAN_MBAR_INIT(mbar_base + 16, 8);   // empty0 (8 CTA arrives)
        SCAN_MBAR_INIT(mbar_base + 24, 8);   // empty1
        SCAN_EXPECT_TX(mbar_base + 0, 1536); // pre-arm phase 0 of both fulls
        SCAN_EXPECT_TX(mbar_base + 8, 1536);
    }
    for (int i = t; i < 2 * HPAD; i += SCAN_THREADS) h_pad[i] = 0.f;
    __syncthreads();
    asm volatile("barrier.cluster.arrive.aligned;" ::: "memory");
    asm volatile("barrier.cluster.wait.aligned;" ::: "memory");

    int phF0 = 0, phF1 = 0, phE0 = 0, phE1 = 0;

    for (int step = 0; step < len; step++) {
        // gx for this step (owner lanes) — issue before any waiting
        float g0 = 0.f, g1 = 0.f, g2 = 0.f, g3 = 0.f;
        if (owner) {
            const float* gp = gxp + (size_t)step * NGATE;
            g0 = __ldg(gp);
            g1 = __ldg(gp + HID);
            g2 = __ldg(gp + 2 * HID);
            g3 = __ldg(gp + 3 * HID);
        }
        // all local threads done with previous step (incl. reads of old buffer)
        __syncthreads();

        if (step > 0) {
            // t0: tell all peers the buffer we read last step is free again
            if (t == 0) {
                int eb = (step - 1) & 1;
                #pragma unroll
                for (int r = 0; r < 8; r++)
                    SCAN_ARRIVE_REMOTE(peer_m[r] + 16 + eb * 8);
            }
            // wait for this step's h (full barrier of buffer step&1)
            int b = step & 1;
            if (b) { SCAN_WAIT(mbar_base + 8, phF1); phF1 ^= 1; }
            else   { SCAN_WAIT(mbar_base + 0, phF0); phF0 ^= 1; }
        }

        // ---- dot: 4 gate rows of unit rb over 48 k-elems ----
        int par = step & 1;
        const float4* h4 = (const float4*)(h_pad + par * HPAD + ks * 52);
        float a0 = 0.f, a1 = 0.f, a2 = 0.f, a3 = 0.f;
        #pragma unroll
        for (int j = 0; j < 12; j++) {
            float4 hv = h4[j];
            float4 v0 = wi[j];
            float4 v1 = wf[j];
            float4 v2 = Ws4[j * 384 + t];
            float4 v3 = Ws4[(12 + j) * 384 + t];
            a0 = fmaf(v0.x, hv.x, a0); a0 = fmaf(v0.y, hv.y, a0);
            a0 = fmaf(v0.z, hv.z, a0); a0 = fmaf(v0.w, hv.w, a0);
            a1 = fmaf(v1.x, hv.x, a1); a1 = fmaf(v1.y, hv.y, a1);
            a1 = fmaf(v1.z, hv.z, a1); a1 = fmaf(v1.w, hv.w, a1);
            a2 = fmaf(v2.x, hv.x, a2); a2 = fmaf(v2.y, hv.y, a2);
            a2 = fmaf(v2.z, hv.z, a2); a2 = fmaf(v2.w, hv.w, a2);
            a3 = fmaf(v3.x, hv.x, a3); a3 = fmaf(v3.y, hv.y, a3);
            a3 = fmaf(v3.z, hv.z, a3); a3 = fmaf(v3.w, hv.w, a3);
        }
        // reduce over the 8 k-slices (lane bits 0..2)
        a0 += __shfl_xor_sync(0xffffffffu, a0, 1);
        a1 += __shfl_xor_sync(0xffffffffu, a1, 1);
        a2 += __shfl_xor_sync(0xffffffffu, a2, 1);
        a3 += __shfl_xor_sync(0xffffffffu, a3, 1);
        a0 += __shfl_xor_sync(0xffffffffu, a0, 2);
        a1 += __shfl_xor_sync(0xffffffffu, a1, 2);
        a2 += __shfl_xor_sync(0xffffffffu, a2, 2);
        a3 += __shfl_xor_sync(0xffffffffu, a3, 2);
        a0 += __shfl_xor_sync(0xffffffffu, a0, 4);
        a1 += __shfl_xor_sync(0xffffffffu, a1, 4);
        a2 += __shfl_xor_sync(0xffffffffu, a2, 4);
        a3 += __shfl_xor_sync(0xffffffffu, a3, 4);

        if (owner) {
            float gi = a0 + g0 + bh0;
            float gf = a1 + g1 + bh1;
            float gg = a2 + g2 + bh2;
            float go = a3 + g3 + bh3;
            c = sigm(gf) * c + sigm(gi) * tanhf(gg);
            float h = sigm(go) * tanhf(c);
            lout[(size_t)step * HID] = h;

            if (step < len - 1) {
                int bw = (step + 1) & 1;
                // wait until every CTA finished reading buffer bw (step-1 dot)
                if (step >= 1) {
                    if (bw) { SCAN_WAIT(mbar_base + 24, phE1); phE1 ^= 1; }
                    else    { SCAN_WAIT(mbar_base + 16, phE0); phE0 ^= 1; }
                }
                // t0 re-arms the full barrier just consumed (next use = step+2)
                // BEFORE its own sends: remote senders to it causally depend on
                // t0's bytes below, so expect_tx precedes every complete_tx.
                if (t == 0 && step >= 1 && step <= len - 3)
                    SCAN_EXPECT_TX(mbar_base + (step & 1) * 8, 1536);
                // push h to all 8 CTAs' buffer bw with tx accounting
                uint32_t off = (uint32_t)(bw * HPAD + (int)rank * 52 + rb) * 4;
                uint32_t hb  = __float_as_uint(h);
                #pragma unroll
                for (int r = 0; r < 8; r++)
                    SCAN_ST_ASYNC(peer_h[r] + off, hb, peer_m[r] + bw * 8);
            }
        }
    }

    asm volatile("barrier.cluster.arrive.aligned;" ::: "memory");
    asm volatile("barrier.cluster.wait.aligned;" ::: "memory");
}

// ============================================================================
// launch — y1 GEMM forked onto a second stream: it depends only on inputs
// (extra, wh2) and runs on the ~20 SMs the 128-CTA scan leaves idle.
// Fork/join via events (capture-legal cross-stream dependency pattern).
// ============================================================================
extern "C" void kernel_launch(void* const* d_in, const int* in_sizes, int n_in,
                              void* d_out, int out_size)
{
    const float* enc    = (const float*)d_in[0];
    const float* extra  = (const float*)d_in[1];
    const int*   forced = (const int*)  d_in[2];
    const int*   lens   = (const int*)  d_in[3];
    const float* emb    = (const float*)d_in[4];
    const float* initt  = (const float*)d_in[5];
    const float* W_ih   = (const float*)d_in[6];
    const float* W_hh   = (const float*)d_in[7];
    const float* b_ih   = (const float*)d_in[8];
    const float* b_hh   = (const float*)d_in[9];
    const float* wh1    = (const float*)d_in[10];
    const float* wh2    = (const float*)d_in[11];
    const float* wsig   = (const float*)d_in[12];

    float* out    = (float*)d_out;
    float* fusion = out;                               // [T,384]
    float* lstm   = out + (size_t)T_TOK * HID;         // [T,384]

    float *Xp, *gxp, *y1p, *x1p;
    cudaGetSymbolAddress((void**)&Xp,  g_X);
    cudaGetSymbolAddress((void**)&gxp, g_gx);
    cudaGetSymbolAddress((void**)&y1p, g_y1);
    cudaGetSymbolAddress((void**)&x1p, g_x1);

    cudaFuncSetAttribute(lstm_scan_kernel,
                         cudaFuncAttributeMaxDynamicSharedMemorySize,
                         SCAN_SMEM_BYTES);

    // side stream + fork/join events (created per call; never destroyed —
    // destroying capture-participating objects mid-capture is illegal, and
    // kernel_launch runs only a couple of times)
    cudaStream_t s2;
    cudaStreamCreateWithFlags(&s2, cudaStreamNonBlocking);
    cudaEvent_t evFork, evJoin;
    cudaEventCreateWithFlags(&evFork, cudaEventDisableTiming);
    cudaEventCreateWithFlags(&evJoin, cudaEventDisableTiming);

    // fork: s2 inherits the capture DAG from the main stream
    cudaEventRecord(evFork, 0);
    cudaStreamWaitEvent(s2, evFork, 0);

    // y1 = tanh(extra) @ wh2^T  — input-only dependency, overlaps everything
    sgemm_k<MODE_TANHA><<<dim3(HID / BN, T_TOK / BM), 256, 0, s2>>>(
        extra, nullptr, wh2, nullptr, y1p, nullptr, nullptr, HID, HID);
    cudaEventRecord(evJoin, s2);

    // main stream: 1) build X
    prepare_kernel<<<(T_TOK * 96 + 255) / 256, 256>>>(enc, forced, lens, emb, initt);

    // 2) gx = X @ W_ih^T + b_ih   [T,1536]
    sgemm_k<MODE_BIAS><<<dim3(NGATE / BN, T_TOK / BM), 256>>>(
        Xp, nullptr, W_ih, b_ih, gxp, nullptr, nullptr, NGATE, HID);

    // 3) LSTM scan -> lstm (second half of d_out); y1 runs on spare SMs
    lstm_scan_kernel<<<128, SCAN_THREADS, SCAN_SMEM_BYTES>>>(gxp, W_hh, b_hh, lens, lstm);

    // 4) x1 = tanh(lstm) @ wh1^T
    sgemm_k<MODE_TANHA><<<dim3(HID / BN, T_TOK / BM), 256>>>(
        lstm, nullptr, wh1, nullptr, x1p, nullptr, nullptr, HID, HID);

    // join: fusion consumes y1
    cudaStreamWaitEvent(0, evJoin, 0);

    // 5) f = sigmoid([x1|y1] @ Wsig^T); fusion epilogue -> first half of d_out
    sgemm_k<MODE_FUSION><<<dim3(HID / BN, T_TOK / BM), 256>>>(
        x1p, y1p, wsig, nullptr, fusion, lstm, extra, HID, 2 * HID);
}

// round 12
// speedup vs baseline: 1.0100x; 1.0011x over previous
#include <cuda_runtime.h>
#include <math.h>
#include <stdint.h>

// ---------------- problem constants (fixed by setup_inputs) ----------------
#define T_TOK 32768
#define HID   384
#define NGATE 1536
#define NSEQ  16

// ---------------- scratch (static device arrays; no allocation) ------------
__device__ float g_X [(size_t)T_TOK * HID];    // [T,384] LSTM input (enc|prev)
__device__ float g_gx[(size_t)T_TOK * NGATE];  // [T,1536] input gate preacts
__device__ float g_y1[(size_t)T_TOK * HID];    // tanh(extra)@wh2^T
__device__ float g_x1[(size_t)T_TOK * HID];    // tanh(lstm)@wh1^T

__device__ __forceinline__ float sigm(float x) { return 1.f / (1.f + expf(-x)); }

// ============================================================================
// prepare: build X = [encoded | prev_label_embedding]
// ============================================================================
__global__ void prepare_kernel(const float* __restrict__ enc,
                               const int*   __restrict__ forced,
                               const int*   __restrict__ lens,
                               const float* __restrict__ emb,
                               const float* __restrict__ initt)
{
    int idx = blockIdx.x * blockDim.x + threadIdx.x;   // T*96 float4 slots
    if (idx >= T_TOK * 96) return;
    int tok = idx / 96;
    int q   = idx - tok * 96;

    float4 v;
    if (q < 64) {
        v = ((const float4*)enc)[(size_t)tok * 64 + q];
    } else {
        bool is64 = (lens[1] == 0);        // int64 layout heuristic (len!=0 always)
        bool is_start = false;
        int srt = 0;
        #pragma unroll
        for (int i = 0; i < NSEQ; i++) {
            if (tok == srt) is_start = true;
            srt += lens[is64 ? 2 * i : i];
        }
        if (is_start) {
            v = ((const float4*)initt)[q - 64];
        } else {
            int fi = forced[is64 ? 2 * (tok - 1) : (tok - 1)];
            v = ((const float4*)(emb + (size_t)fi * 128))[q - 64];
        }
    }
    ((float4*)g_X)[(size_t)tok * 96 + q] = v;
}

// ============================================================================
// SGEMM (PROVEN R2 version): C = opA(A) @ B^T (+epilogue)
// BM=BN=128, BK=16, 256 threads, 8x8 micro-tile.
// ============================================================================
#define BM 128
#define BN 128
#define BK 16

#define MODE_BIAS   0
#define MODE_TANHA  1
#define MODE_FUSION 2

__device__ __forceinline__ float fuse_elem(float pre, float L, float Ev)
{
    float f  = 1.f / (1.f + expf(-pre));
    float x0 = tanhf(L);
    float y0 = tanhf(Ev);
    float x2 = f * x0 + L;
    float y2 = (1.f - f) * y0 + Ev;
    return f * x2 + (1.f - f) * y2;
}

template<int MODE>
__global__ __launch_bounds__(256)
void sgemm_k(const float* __restrict__ A, const float* __restrict__ A2,
             const float* __restrict__ B, const float* __restrict__ bias,
             float* __restrict__ C,
             const float* __restrict__ E1, const float* __restrict__ E2,
             int N, int K)
{
    __shared__ float As[BK][BM + 4];
    __shared__ float Bs[BK][BN + 4];

    int tid = threadIdx.x;
    int m0  = blockIdx.y * BM;
    int n0  = blockIdx.x * BN;
    int tx  = tid & 15;
    int ty  = tid >> 4;

    float acc[8][8];
    #pragma unroll
    for (int i = 0; i < 8; i++)
        #pragma unroll
        for (int j = 0; j < 8; j++) acc[i][j] = 0.f;

    for (int k0 = 0; k0 < K; k0 += BK) {
        #pragma unroll
        for (int i = 0; i < 2; i++) {
            int f  = tid + i * 256;
            int r  = f >> 2;
            int kq = f & 3;
            const float* src;
            if (MODE == MODE_FUSION) {
                src = (k0 < 384) ? (A  + (size_t)(m0 + r) * 384 + k0)
                                 : (A2 + (size_t)(m0 + r) * 384 + (k0 - 384));
            } else {
                src = A + (size_t)(m0 + r) * K + k0;
            }
            float4 v = *(const float4*)(src + kq * 4);
            if (MODE == MODE_TANHA) {
                v.x = tanhf(v.x); v.y = tanhf(v.y);
                v.z = tanhf(v.z); v.w = tanhf(v.w);
            }
            As[kq * 4 + 0][r] = v.x; As[kq * 4 + 1][r] = v.y;
            As[kq * 4 + 2][r] = v.z; As[kq * 4 + 3][r] = v.w;
        }
        #pragma unroll
        for (int i = 0; i < 2; i++) {
            int f  = tid + i * 256;
            int r  = f >> 2;
            int kq = f & 3;
            float4 v = *(const float4*)(B + (size_t)(n0 + r) * K + k0 + kq * 4);
            Bs[kq * 4 + 0][r] = v.x; Bs[kq * 4 + 1][r] = v.y;
            Bs[kq * 4 + 2][r] = v.z; Bs[kq * 4 + 3][r] = v.w;
        }
        __syncthreads();

        #pragma unroll
        for (int kk = 0; kk < BK; kk++) {
            float a[8], b[8];
            float4 a0 = *(const float4*)&As[kk][ty * 8];
            float4 a1 = *(const float4*)&As[kk][ty * 8 + 4];
            float4 b0 = *(const float4*)&Bs[kk][tx * 8];
            float4 b1 = *(const float4*)&Bs[kk][tx * 8 + 4];
            a[0]=a0.x; a[1]=a0.y; a[2]=a0.z; a[3]=a0.w;
            a[4]=a1.x; a[5]=a1.y; a[6]=a1.z; a[7]=a1.w;
            b[0]=b0.x; b[1]=b0.y; b[2]=b0.z; b[3]=b0.w;
            b[4]=b1.x; b[5]=b1.y; b[6]=b1.z; b[7]=b1.w;
            #pragma unroll
            for (int i = 0; i < 8; i++)
                #pragma unroll
                for (int j = 0; j < 8; j++)
                    acc[i][j] = fmaf(a[i], b[j], acc[i][j]);
        }
        __syncthreads();
    }

    #pragma unroll
    for (int i = 0; i < 8; i++) {
        size_t m = (size_t)(m0 + ty * 8 + i);
        #pragma unroll
        for (int q = 0; q < 2; q++) {
            int n = n0 + tx * 8 + q * 4;
            float r0 = acc[i][q * 4 + 0], r1 = acc[i][q * 4 + 1];
            float r2 = acc[i][q * 4 + 2], r3 = acc[i][q * 4 + 3];
            if (MODE == MODE_BIAS) {
                float4 bv = *(const float4*)(bias + n);
                r0 += bv.x; r1 += bv.y; r2 += bv.z; r3 += bv.w;
            }
            if (MODE == MODE_FUSION) {
                float4 L = *(const float4*)(E1 + m * 384 + n);
                float4 E = *(const float4*)(E2 + m * 384 + n);
                r0 = fuse_elem(r0, L.x, E.x); r1 = fuse_elem(r1, L.y, E.y);
                r2 = fuse_elem(r2, L.z, E.z); r3 = fuse_elem(r3, L.w, E.w);
            }
            float4 ov = make_float4(r0, r1, r2, r3);
            *(float4*)(C + m * N + n) = ov;
        }
    }
}

// ============================================================================
// LSTM scan v5: structure identical to the PASSING v3 scan; the dot product
// now uses packed fma.rn.f32x2 — 96 FMA2 instr/thread (was 192 FFMA), and
// per-accumulator dependency chains of 24 (was 48).
// ============================================================================
#define SCAN_THREADS 384
#define WS_FLOATS (24 * 384 * 4)     // 96 floats/thread of W in smem
#define HPAD 416                     // 8 chunks * 52 floats
#define MBAR_OFF ((WS_FLOATS + 2 * HPAD) * 4)
#define SCAN_SMEM_BYTES (MBAR_OFF + 64)

#define SCAN_MBAR_INIT(addr, cnt) \
    asm volatile("mbarrier.init.shared.b64 [%0], %1;" :: "r"(addr), "r"(cnt) : "memory")
#define SCAN_EXPECT_TX(addr, tx) \
    asm volatile("mbarrier.arrive.expect_tx.shared.b64 _, [%0], %1;" :: "r"(addr), "r"(tx) : "memory")
#define SCAN_ARRIVE_REMOTE(addr) \
    asm volatile("mbarrier.arrive.shared::cluster.b64 _, [%0];" :: "r"(addr) : "memory")
#define SCAN_ST_ASYNC(addr, val, mbar) \
    asm volatile("st.async.weak.shared::cluster.mbarrier::complete_tx::bytes.b32 [%0], %1, [%2];" \
                 :: "r"(addr), "r"(val), "r"(mbar) : "memory")
#define SCAN_WAIT(mbar, parity) do {                                           \
    uint32_t _done;                                                            \
    asm volatile("{\n\t.reg .pred p;\n\t"                                      \
      "mbarrier.try_wait.parity.acquire.cluster.shared::cta.b64 p, [%1], %2;\n\t" \
      "selp.b32 %0, 1, 0, p;\n\t}" : "=r"(_done) : "r"(mbar), "r"(parity) : "memory"); \
    while (!_done) {                                                           \
      asm volatile("{\n\t.reg .pred p;\n\t"                                    \
        "mbarrier.try_wait.parity.acquire.cluster.shared::cta.b64 p, [%1], %2, 0x989680;\n\t" \
        "selp.b32 %0, 1, 0, p;\n\t}" : "=r"(_done) : "r"(mbar), "r"(parity) : "memory"); \
    }                                                                          \
} while (0)

// packed f32x2 fma: d = a*b + c elementwise on 2 packed floats
#define FMA2(d, a, b, c) \
    asm("fma.rn.f32x2 %0, %1, %2, %3;" : "=l"(d) : "l"(a), "l"(b), "l"(c))

typedef unsigned long long u64;
union F4U {
    float4 f;
    ulonglong2 u;
};
union U64F2 {
    u64 u;
    float2 f;
};

__global__ void __cluster_dims__(8, 1, 1) __launch_bounds__(SCAN_THREADS, 1)
lstm_scan_kernel(const float* __restrict__ gx, const float* __restrict__ W_hh,
                 const float* __restrict__ b_hh, const int* __restrict__ lens,
                 float* __restrict__ lstm)
{
    extern __shared__ float sm[];
    float4* Ws4   = (float4*)sm;          // [24][384] float4 (gates g,o)
    float*  h_pad = sm + WS_FLOATS;       // [2][HPAD]

    uint32_t smem_base;
    asm("{ .reg .u64 u; cvta.to.shared.u64 u, %1; cvt.u32.u64 %0, u; }"
        : "=r"(smem_base) : "l"(sm));
    uint32_t hpad_base = smem_base + WS_FLOATS * 4;
    uint32_t mbar_base = smem_base + MBAR_OFF;   // full0@0 full1@8 empty0@16 empty1@24

    int t = threadIdx.x;
    uint32_t rank;
    asm("mov.u32 %0, %%cluster_ctarank;" : "=r"(rank));
    int seq = blockIdx.x >> 3;

    bool is64 = (lens[1] == 0);
    int start = 0;
    for (int i = 0; i < seq; i++) start += lens[is64 ? 2 * i : i];
    int len = lens[is64 ? 2 * seq : seq];

    int ks    = t & 7;        // k-slice: k in [ks*48, ks*48+48)
    int rb    = t >> 3;       // hidden unit (local 0..47)
    int kbase = ks * 48;
    bool owner = (ks == 0);

    // ---- stage W: gates i,f -> registers (as packed f32x2); g,o -> smem ----
    ulonglong2 wi[12], wf[12];
    #pragma unroll
    for (int g = 0; g < 4; g++) {
        int grow = g * HID + (int)rank * 48 + rb;
        const float4* src = (const float4*)(W_hh + (size_t)grow * HID + kbase);
        if (g == 0) {
            #pragma unroll
            for (int j = 0; j < 12; j++) { F4U v; v.f = src[j]; wi[j] = v.u; }
        } else if (g == 1) {
            #pragma unroll
            for (int j = 0; j < 12; j++) { F4U v; v.f = src[j]; wf[j] = v.u; }
        } else {
            #pragma unroll
            for (int j = 0; j < 12; j++) Ws4[((g - 2) * 12 + j) * 384 + t] = src[j];
        }
    }

    // ---- owner-lane state ----
    float c = 0.f, bh0 = 0.f, bh1 = 0.f, bh2 = 0.f, bh3 = 0.f;
    const float* gxp  = gx;
    float*       lout = lstm;
    if (owner) {
        int u = (int)rank * 48 + rb;
        bh0 = b_hh[u];            bh1 = b_hh[HID + u];
        bh2 = b_hh[2 * HID + u];  bh3 = b_hh[3 * HID + u];
        gxp  = gx   + (size_t)start * NGATE + u;
        lout = lstm + (size_t)start * HID   + u;
    }

    // ---- peer base addresses (h_pad and mbar block in each cluster CTA) ----
    uint32_t peer_h[8], peer_m[8];
    #pragma unroll
    for (int r = 0; r < 8; r++) {
        asm("mapa.shared::cluster.u32 %0, %1, %2;" : "=r"(peer_h[r]) : "r"(hpad_base), "r"(r));
        asm("mapa.shared::cluster.u32 %0, %1, %2;" : "=r"(peer_m[r]) : "r"(mbar_base), "r"(r));
    }

    // ---- init: mbars + zero h buffers, publish to cluster ----
    if (t == 0) {
        SCAN_MBAR_INIT(mbar_base + 0, 1);    // full0 (tx-based)
        SCAN_MBAR_INIT(mbar_base + 8, 1);    // full1
        SCAN_MBAR_INIT(mbar_base + 16, 8);   // empty0 (8 CTA arrives)
        SCAN_MBAR_INIT(mbar_base + 24, 8);   // empty1
        SCAN_EXPECT_TX(mbar_base + 0, 1536); // pre-arm phase 0 of both fulls
        SCAN_EXPECT_TX(mbar_base + 8, 1536);
    }
    for (int i = t; i < 2 * HPAD; i += SCAN_THREADS) h_pad[i] = 0.f;
    __syncthreads();
    asm volatile("barrier.cluster.arrive.aligned;" ::: "memory");
    asm volatile("barrier.cluster.wait.aligned;" ::: "memory");

    int phF0 = 0, phF1 = 0, phE0 = 0, phE1 = 0;

    for (int step = 0; step < len; step++) {
        // gx for this step (owner lanes) — issue before any waiting
        float g0 = 0.f, g1 = 0.f, g2 = 0.f, g3 = 0.f;
        if (owner) {
            const float* gp = gxp + (size_t)step * NGATE;
            g0 = __ldg(gp);
            g1 = __ldg(gp + HID);
            g2 = __ldg(gp + 2 * HID);
            g3 = __ldg(gp + 3 * HID);
        }
        // all local threads done with previous step (incl. reads of old buffer)
        __syncthreads();

        if (step > 0) {
            // t0: tell all peers the buffer we read last step is free again
            if (t == 0) {
                int eb = (step - 1) & 1;
                #pragma unroll
                for (int r = 0; r < 8; r++)
                    SCAN_ARRIVE_REMOTE(peer_m[r] + 16 + eb * 8);
            }
            // wait for this step's h (full barrier of buffer step&1)
            int b = step & 1;
            if (b) { SCAN_WAIT(mbar_base + 8, phF1); phF1 ^= 1; }
            else   { SCAN_WAIT(mbar_base + 0, phF0); phF0 ^= 1; }
        }

        // ---- dot: 4 gate rows of unit rb over 48 k-elems (packed f32x2) ----
        int par = step & 1;
        const float4* h4 = (const float4*)(h_pad + par * HPAD + ks * 52);
        u64 q0 = 0, q1 = 0, q2 = 0, q3 = 0;   // f32x2 accumulators (0.0f,0.0f)
        #pragma unroll
        for (int j = 0; j < 12; j++) {
            F4U hv; hv.f = h4[j];
            F4U v2; v2.f = Ws4[j * 384 + t];
            F4U v3; v3.f = Ws4[(12 + j) * 384 + t];
            FMA2(q0, wi[j].x, hv.u.x, q0); FMA2(q0, wi[j].y, hv.u.y, q0);
            FMA2(q1, wf[j].x, hv.u.x, q1); FMA2(q1, wf[j].y, hv.u.y, q1);
            FMA2(q2, v2.u.x, hv.u.x, q2);  FMA2(q2, v2.u.y, hv.u.y, q2);
            FMA2(q3, v3.u.x, hv.u.x, q3);  FMA2(q3, v3.u.y, hv.u.y, q3);
        }
        float a0, a1, a2, a3;
        { U64F2 z; z.u = q0; a0 = z.f.x + z.f.y; }
        { U64F2 z; z.u = q1; a1 = z.f.x + z.f.y; }
        { U64F2 z; z.u = q2; a2 = z.f.x + z.f.y; }
        { U64F2 z; z.u = q3; a3 = z.f.x + z.f.y; }

        // reduce over the 8 k-slices (lane bits 0..2)
        a0 += __shfl_xor_sync(0xffffffffu, a0, 1);
        a1 += __shfl_xor_sync(0xffffffffu, a1, 1);
        a2 += __shfl_xor_sync(0xffffffffu, a2, 1);
        a3 += __shfl_xor_sync(0xffffffffu, a3, 1);
        a0 += __shfl_xor_sync(0xffffffffu, a0, 2);
        a1 += __shfl_xor_sync(0xffffffffu, a1, 2);
        a2 += __shfl_xor_sync(0xffffffffu, a2, 2);
        a3 += __shfl_xor_sync(0xffffffffu, a3, 2);
        a0 += __shfl_xor_sync(0xffffffffu, a0, 4);
        a1 += __shfl_xor_sync(0xffffffffu, a1, 4);
        a2 += __shfl_xor_sync(0xffffffffu, a2, 4);
        a3 += __shfl_xor_sync(0xffffffffu, a3, 4);

        if (owner) {
            float gi = a0 + g0 + bh0;
            float gf = a1 + g1 + bh1;
            float gg = a2 + g2 + bh2;
            float go = a3 + g3 + bh3;
            c = sigm(gf) * c + sigm(gi) * tanhf(gg);
            float h = sigm(go) * tanhf(c);
            lout[(size_t)step * HID] = h;

            if (step < len - 1) {
                int bw = (step + 1) & 1;
                // wait until every CTA finished reading buffer bw (step-1 dot)
                if (step >= 1) {
                    if (bw) { SCAN_WAIT(mbar_base + 24, phE1); phE1 ^= 1; }
                    else    { SCAN_WAIT(mbar_base + 16, phE0); phE0 ^= 1; }
                }
                // t0 re-arms the full barrier just consumed (next use = step+2)
                // BEFORE its own sends: remote senders to it causally depend on
                // t0's bytes below, so expect_tx precedes every complete_tx.
                if (t == 0 && step >= 1 && step <= len - 3)
                    SCAN_EXPECT_TX(mbar_base + (step & 1) * 8, 1536);
                // push h to all 8 CTAs' buffer bw with tx accounting
                uint32_t off = (uint32_t)(bw * HPAD + (int)rank * 52 + rb) * 4;
                uint32_t hb  = __float_as_uint(h);
                #pragma unroll
                for (int r = 0; r < 8; r++)
                    SCAN_ST_ASYNC(peer_h[r] + off, hb, peer_m[r] + bw * 8);
            }
        }
    }

    asm volatile("barrier.cluster.arrive.aligned;" ::: "memory");
    asm volatile("barrier.cluster.wait.aligned;" ::: "memory");
}

// ============================================================================
// launch — y1 GEMM forked onto a second stream (proven R11 pattern).
// ============================================================================
extern "C" void kernel_launch(void* const* d_in, const int* in_sizes, int n_in,
                              void* d_out, int out_size)
{
    const float* enc    = (const float*)d_in[0];
    const float* extra  = (const float*)d_in[1];
    const int*   forced = (const int*)  d_in[2];
    const int*   lens   = (const int*)  d_in[3];
    const float* emb    = (const float*)d_in[4];
    const float* initt  = (const float*)d_in[5];
    const float* W_ih   = (const float*)d_in[6];
    const float* W_hh   = (const float*)d_in[7];
    const float* b_ih   = (const float*)d_in[8];
    const float* b_hh   = (const float*)d_in[9];
    const float* wh1    = (const float*)d_in[10];
    const float* wh2    = (const float*)d_in[11];
    const float* wsig   = (const float*)d_in[12];

    float* out    = (float*)d_out;
    float* fusion = out;                               // [T,384]
    float* lstm   = out + (size_t)T_TOK * HID;         // [T,384]

    float *Xp, *gxp, *y1p, *x1p;
    cudaGetSymbolAddress((void**)&Xp,  g_X);
    cudaGetSymbolAddress((void**)&gxp, g_gx);
    cudaGetSymbolAddress((void**)&y1p, g_y1);
    cudaGetSymbolAddress((void**)&x1p, g_x1);

    cudaFuncSetAttribute(lstm_scan_kernel,
                         cudaFuncAttributeMaxDynamicSharedMemorySize,
                         SCAN_SMEM_BYTES);

    // side stream + fork/join events (created per call; never destroyed —
    // destroying capture-participating objects mid-capture is illegal, and
    // kernel_launch runs only a couple of times)
    cudaStream_t s2;
    cudaStreamCreateWithFlags(&s2, cudaStreamNonBlocking);
    cudaEvent_t evFork, evJoin;
    cudaEventCreateWithFlags(&evFork, cudaEventDisableTiming);
    cudaEventCreateWithFlags(&evJoin, cudaEventDisableTiming);

    // fork: s2 inherits the capture DAG from the main stream
    cudaEventRecord(evFork, 0);
    cudaStreamWaitEvent(s2, evFork, 0);

    // y1 = tanh(extra) @ wh2^T  — input-only dependency, overlaps everything
    sgemm_k<MODE_TANHA><<<dim3(HID / BN, T_TOK / BM), 256, 0, s2>>>(
        extra, nullptr, wh2, nullptr, y1p, nullptr, nullptr, HID, HID);
    cudaEventRecord(evJoin, s2);

    // main stream: 1) build X
    prepare_kernel<<<(T_TOK * 96 + 255) / 256, 256>>>(enc, forced, lens, emb, initt);

    // 2) gx = X @ W_ih^T + b_ih   [T,1536]
    sgemm_k<MODE_BIAS><<<dim3(NGATE / BN, T_TOK / BM), 256>>>(
        Xp, nullptr, W_ih, b_ih, gxp, nullptr, nullptr, NGATE, HID);

    // 3) LSTM scan -> lstm (second half of d_out); y1 runs on spare SMs
    lstm_scan_kernel<<<128, SCAN_THREADS, SCAN_SMEM_BYTES>>>(gxp, W_hh, b_hh, lens, lstm);

    // 4) x1 = tanh(lstm) @ wh1^T
    sgemm_k<MODE_TANHA><<<dim3(HID / BN, T_TOK / BM), 256>>>(
        lstm, nullptr, wh1, nullptr, x1p, nullptr, nullptr, HID, HID);

    // join: fusion consumes y1
    cudaStreamWaitEvent(0, evJoin, 0);

    // 5) f = sigmoid([x1|y1] @ Wsig^T); fusion epilogue -> first half of d_out
    sgemm_k<MODE_FUSION><<<dim3(HID / BN, T_TOK / BM), 256>>>(
        x1p, y1p, wsig, nullptr, fusion, lstm, extra, HID, 2 * HID);
}

// round 14
// speedup vs baseline: 1.0955x; 1.0847x over previous
#include <cuda_runtime.h>
#include <math.h>
#include <stdint.h>

// ---------------- problem constants (fixed by setup_inputs) ----------------
#define T_TOK 32768
#define HID   384
#define NGATE 1536
#define NSEQ  16

// ---------------- scratch (static device arrays; no allocation) ------------
__device__ float g_X [(size_t)T_TOK * HID];    // [T,384] LSTM input (enc|prev)
__device__ float g_gx[(size_t)T_TOK * NGATE];  // [T,1536] input gate preacts
__device__ float g_y1[(size_t)T_TOK * HID];    // tanh(extra)@wh2^T
__device__ float g_x1[(size_t)T_TOK * HID];    // tanh(lstm)@wh1^T

__device__ __forceinline__ float sigm(float x) { return 1.f / (1.f + expf(-x)); }

// fast MUFU-based pointwise for the scan (accuracy-preserving forms)
#define LOG2E 1.4426950408889634f
__device__ __forceinline__ float sigm_fast(float x)
{
    float e;
    asm("ex2.approx.f32 %0, %1;" : "=f"(e) : "f"(-x * LOG2E));
    float r;
    asm("rcp.approx.f32 %0, %1;" : "=f"(r) : "f"(1.f + e));
    return r;
}
__device__ __forceinline__ float tanh_fast(float x)
{
    // tanh(x) = 1 - 2/(1+e^{2x}); safe at both tails (no inf/inf)
    float e;
    asm("ex2.approx.f32 %0, %1;" : "=f"(e) : "f"(x * (2.f * LOG2E)));
    float r;
    asm("rcp.approx.f32 %0, %1;" : "=f"(r) : "f"(1.f + e));
    return 1.f - 2.f * r;
}

// ============================================================================
// prepare: build X = [encoded | prev_label_embedding]
// ============================================================================
__global__ void prepare_kernel(const float* __restrict__ enc,
                               const int*   __restrict__ forced,
                               const int*   __restrict__ lens,
                               const float* __restrict__ emb,
                               const float* __restrict__ initt)
{
    int idx = blockIdx.x * blockDim.x + threadIdx.x;   // T*96 float4 slots
    if (idx >= T_TOK * 96) return;
    int tok = idx / 96;
    int q   = idx - tok * 96;

    float4 v;
    if (q < 64) {
        v = ((const float4*)enc)[(size_t)tok * 64 + q];
    } else {
        bool is64 = (lens[1] == 0);        // int64 layout heuristic (len!=0 always)
        bool is_start = false;
        int srt = 0;
        #pragma unroll
        for (int i = 0; i < NSEQ; i++) {
            if (tok == srt) is_start = true;
            srt += lens[is64 ? 2 * i : i];
        }
        if (is_start) {
            v = ((const float4*)initt)[q - 64];
        } else {
            int fi = forced[is64 ? 2 * (tok - 1) : (tok - 1)];
            v = ((const float4*)(emb + (size_t)fi * 128))[q - 64];
        }
    }
    ((float4*)g_X)[(size_t)tok * 96 + q] = v;
}

// ============================================================================
// SGEMM (PROVEN R2 version): C = opA(A) @ B^T (+epilogue)
// BM=BN=128, BK=16, 256 threads, 8x8 micro-tile.
// ============================================================================
#define BM 128
#define BN 128
#define BK 16

#define MODE_BIAS   0
#define MODE_TANHA  1
#define MODE_FUSION 2

__device__ __forceinline__ float fuse_elem(float pre, float L, float Ev)
{
    float f  = 1.f / (1.f + expf(-pre));
    float x0 = tanhf(L);
    float y0 = tanhf(Ev);
    float x2 = f * x0 + L;
    float y2 = (1.f - f) * y0 + Ev;
    return f * x2 + (1.f - f) * y2;
}

template<int MODE>
__global__ __launch_bounds__(256)
void sgemm_k(const float* __restrict__ A, const float* __restrict__ A2,
             const float* __restrict__ B, const float* __restrict__ bias,
             float* __restrict__ C,
             const float* __restrict__ E1, const float* __restrict__ E2,
             int N, int K)
{
    __shared__ float As[BK][BM + 4];
    __shared__ float Bs[BK][BN + 4];

    int tid = threadIdx.x;
    int m0  = blockIdx.y * BM;
    int n0  = blockIdx.x * BN;
    int tx  = tid & 15;
    int ty  = tid >> 4;

    float acc[8][8];
    #pragma unroll
    for (int i = 0; i < 8; i++)
        #pragma unroll
        for (int j = 0; j < 8; j++) acc[i][j] = 0.f;

    for (int k0 = 0; k0 < K; k0 += BK) {
        #pragma unroll
        for (int i = 0; i < 2; i++) {
            int f  = tid + i * 256;
            int r  = f >> 2;
            int kq = f & 3;
            const float* src;
            if (MODE == MODE_FUSION) {
                src = (k0 < 384) ? (A  + (size_t)(m0 + r) * 384 + k0)
                                 : (A2 + (size_t)(m0 + r) * 384 + (k0 - 384));
            } else {
                src = A + (size_t)(m0 + r) * K + k0;
            }
            float4 v = *(const float4*)(src + kq * 4);
            if (MODE == MODE_TANHA) {
                v.x = tanhf(v.x); v.y = tanhf(v.y);
                v.z = tanhf(v.z); v.w = tanhf(v.w);
            }
            As[kq * 4 + 0][r] = v.x; As[kq * 4 + 1][r] = v.y;
            As[kq * 4 + 2][r] = v.z; As[kq * 4 + 3][r] = v.w;
        }
        #pragma unroll
        for (int i = 0; i < 2; i++) {
            int f  = tid + i * 256;
            int r  = f >> 2;
            int kq = f & 3;
            float4 v = *(const float4*)(B + (size_t)(n0 + r) * K + k0 + kq * 4);
            Bs[kq * 4 + 0][r] = v.x; Bs[kq * 4 + 1][r] = v.y;
            Bs[kq * 4 + 2][r] = v.z; Bs[kq * 4 + 3][r] = v.w;
        }
        __syncthreads();

        #pragma unroll
        for (int kk = 0; kk < BK; kk++) {
            float a[8], b[8];
            float4 a0 = *(const float4*)&As[kk][ty * 8];
            float4 a1 = *(const float4*)&As[kk][ty * 8 + 4];
            float4 b0 = *(const float4*)&Bs[kk][tx * 8];
            float4 b1 = *(const float4*)&Bs[kk][tx * 8 + 4];
            a[0]=a0.x; a[1]=a0.y; a[2]=a0.z; a[3]=a0.w;
            a[4]=a1.x; a[5]=a1.y; a[6]=a1.z; a[7]=a1.w;
            b[0]=b0.x; b[1]=b0.y; b[2]=b0.z; b[3]=b0.w;
            b[4]=b1.x; b[5]=b1.y; b[6]=b1.z; b[7]=b1.w;
            #pragma unroll
            for (int i = 0; i < 8; i++)
                #pragma unroll
                for (int j = 0; j < 8; j++)
                    acc[i][j] = fmaf(a[i], b[j], acc[i][j]);
        }
        __syncthreads();
    }

    #pragma unroll
    for (int i = 0; i < 8; i++) {
        size_t m = (size_t)(m0 + ty * 8 + i);
        #pragma unroll
        for (int q = 0; q < 2; q++) {
            int n = n0 + tx * 8 + q * 4;
            float r0 = acc[i][q * 4 + 0], r1 = acc[i][q * 4 + 1];
            float r2 = acc[i][q * 4 + 2], r3 = acc[i][q * 4 + 3];
            if (MODE == MODE_BIAS) {
                float4 bv = *(const float4*)(bias + n);
                r0 += bv.x; r1 += bv.y; r2 += bv.z; r3 += bv.w;
            }
            if (MODE == MODE_FUSION) {
                float4 L = *(const float4*)(E1 + m * 384 + n);
                float4 E = *(const float4*)(E2 + m * 384 + n);
                r0 = fuse_elem(r0, L.x, E.x); r1 = fuse_elem(r1, L.y, E.y);
                r2 = fuse_elem(r2, L.z, E.z); r3 = fuse_elem(r3, L.w, E.w);
            }
            float4 ov = make_float4(r0, r1, r2, r3);
            *(float4*)(C + m * N + n) = ov;
        }
    }
}

// ============================================================================
// LSTM scan v6: identical structure to the PASSING v5 scan (f32x2 dot,
// mbarrier protocol); the pointwise now uses MUFU ex2/rcp-based sigmoid and
// tanh (the library expf/tanhf sequences were ~95 instr issued by all 12
// warps — the largest soft term left on the per-step critical path).
// ============================================================================
#define SCAN_THREADS 384
#define WS_FLOATS (24 * 384 * 4)     // 96 floats/thread of W in smem
#define HPAD 416                     // 8 chunks * 52 floats
#define MBAR_OFF ((WS_FLOATS + 2 * HPAD) * 4)
#define SCAN_SMEM_BYTES (MBAR_OFF + 64)

#define SCAN_MBAR_INIT(addr, cnt) \
    asm volatile("mbarrier.init.shared.b64 [%0], %1;" :: "r"(addr), "r"(cnt) : "memory")
#define SCAN_EXPECT_TX(addr, tx) \
    asm volatile("mbarrier.arrive.expect_tx.shared.b64 _, [%0], %1;" :: "r"(addr), "r"(tx) : "memory")
#define SCAN_ARRIVE_REMOTE(addr) \
    asm volatile("mbarrier.arrive.shared::cluster.b64 _, [%0];" :: "r"(addr) : "memory")
#define SCAN_ST_ASYNC(addr, val, mbar) \
    asm volatile("st.async.weak.shared::cluster.mbarrier::complete_tx::bytes.b32 [%0], %1, [%2];" \
                 :: "r"(addr), "r"(val), "r"(mbar) : "memory")
#define SCAN_WAIT(mbar, parity) do {                                           \
    uint32_t _done;                                                            \
    asm volatile("{\n\t.reg .pred p;\n\t"                                      \
      "mbarrier.try_wait.parity.acquire.cluster.shared::cta.b64 p, [%1], %2;\n\t" \
      "selp.b32 %0, 1, 0, p;\n\t}" : "=r"(_done) : "r"(mbar), "r"(parity) : "memory"); \
    while (!_done) {                                                           \
      asm volatile("{\n\t.reg .pred p;\n\t"                                    \
        "mbarrier.try_wait.parity.acquire.cluster.shared::cta.b64 p, [%1], %2, 0x989680;\n\t" \
        "selp.b32 %0, 1, 0, p;\n\t}" : "=r"(_done) : "r"(mbar), "r"(parity) : "memory"); \
    }                                                                          \
} while (0)

// packed f32x2 fma: d = a*b + c elementwise on 2 packed floats
#define FMA2(d, a, b, c) \
    asm("fma.rn.f32x2 %0, %1, %2, %3;" : "=l"(d) : "l"(a), "l"(b), "l"(c))

typedef unsigned long long u64;
union F4U {
    float4 f;
    ulonglong2 u;
};
union U64F2 {
    u64 u;
    float2 f;
};

__global__ void __cluster_dims__(8, 1, 1) __launch_bounds__(SCAN_THREADS, 1)
lstm_scan_kernel(const float* __restrict__ gx, const float* __restrict__ W_hh,
                 const float* __restrict__ b_hh, const int* __restrict__ lens,
                 float* __restrict__ lstm)
{
    extern __shared__ float sm[];
    float4* Ws4   = (float4*)sm;          // [24][384] float4 (gates g,o)
    float*  h_pad = sm + WS_FLOATS;       // [2][HPAD]

    uint32_t smem_base;
    asm("{ .reg .u64 u; cvta.to.shared.u64 u, %1; cvt.u32.u64 %0, u; }"
        : "=r"(smem_base) : "l"(sm));
    uint32_t hpad_base = smem_base + WS_FLOATS * 4;
    uint32_t mbar_base = smem_base + MBAR_OFF;   // full0@0 full1@8 empty0@16 empty1@24

    int t = threadIdx.x;
    uint32_t rank;
    asm("mov.u32 %0, %%cluster_ctarank;" : "=r"(rank));
    int seq = blockIdx.x >> 3;

    bool is64 = (lens[1] == 0);
    int start = 0;
    for (int i = 0; i < seq; i++) start += lens[is64 ? 2 * i : i];
    int len = lens[is64 ? 2 * seq : seq];

    int ks    = t & 7;        // k-slice: k in [ks*48, ks*48+48)
    int rb    = t >> 3;       // hidden unit (local 0..47)
    int kbase = ks * 48;
    bool owner = (ks == 0);

    // ---- stage W: gates i,f -> registers (as packed f32x2); g,o -> smem ----
    ulonglong2 wi[12], wf[12];
    #pragma unroll
    for (int g = 0; g < 4; g++) {
        int grow = g * HID + (int)rank * 48 + rb;
        const float4* src = (const float4*)(W_hh + (size_t)grow * HID + kbase);
        if (g == 0) {
            #pragma unroll
            for (int j = 0; j < 12; j++) { F4U v; v.f = src[j]; wi[j] = v.u; }
        } else if (g == 1) {
            #pragma unroll
            for (int j = 0; j < 12; j++) { F4U v; v.f = src[j]; wf[j] = v.u; }
        } else {
            #pragma unroll
            for (int j = 0; j < 12; j++) Ws4[((g - 2) * 12 + j) * 384 + t] = src[j];
        }
    }

    // ---- owner-lane state ----
    float c = 0.f, bh0 = 0.f, bh1 = 0.f, bh2 = 0.f, bh3 = 0.f;
    const float* gxp  = gx;
    float*       lout = lstm;
    if (owner) {
        int u = (int)rank * 48 + rb;
        bh0 = b_hh[u];            bh1 = b_hh[HID + u];
        bh2 = b_hh[2 * HID + u];  bh3 = b_hh[3 * HID + u];
        gxp  = gx   + (size_t)start * NGATE + u;
        lout = lstm + (size_t)start * HID   + u;
    }

    // ---- peer base addresses (h_pad and mbar block in each cluster CTA) ----
    uint32_t peer_h[8], peer_m[8];
    #pragma unroll
    for (int r = 0; r < 8; r++) {
        asm("mapa.shared::cluster.u32 %0, %1, %2;" : "=r"(peer_h[r]) : "r"(hpad_base), "r"(r));
        asm("mapa.shared::cluster.u32 %0, %1, %2;" : "=r"(peer_m[r]) : "r"(mbar_base), "r"(r));
    }

    // ---- init: mbars + zero h buffers, publish to cluster ----
    if (t == 0) {
        SCAN_MBAR_INIT(mbar_base + 0, 1);    // full0 (tx-based)
        SCAN_MBAR_INIT(mbar_base + 8, 1);    // full1
        SCAN_MBAR_INIT(mbar_base + 16, 8);   // empty0 (8 CTA arrives)
        SCAN_MBAR_INIT(mbar_base + 24, 8);   // empty1
        SCAN_EXPECT_TX(mbar_base + 0, 1536); // pre-arm phase 0 of both fulls
        SCAN_EXPECT_TX(mbar_base + 8, 1536);
    }
    for (int i = t; i < 2 * HPAD; i += SCAN_THREADS) h_pad[i] = 0.f;
    __syncthreads();
    asm volatile("barrier.cluster.arrive.aligned;" ::: "memory");
    asm volatile("barrier.cluster.wait.aligned;" ::: "memory");

    int phF0 = 0, phF1 = 0, phE0 = 0, phE1 = 0;

    for (int step = 0; step < len; step++) {
        // gx for this step (owner lanes) — issue before any waiting
        float g0 = 0.f, g1 = 0.f, g2 = 0.f, g3 = 0.f;
        if (owner) {
            const float* gp = gxp + (size_t)step * NGATE;
            g0 = __ldg(gp);
            g1 = __ldg(gp + HID);
            g2 = __ldg(gp + 2 * HID);
            g3 = __ldg(gp + 3 * HID);
        }
        // all local threads done with previous step (incl. reads of old buffer)
        __syncthreads();

        if (step > 0) {
            // t0: tell all peers the buffer we read last step is free again
            if (t == 0) {
                int eb = (step - 1) & 1;
                #pragma unroll
                for (int r = 0; r < 8; r++)
                    SCAN_ARRIVE_REMOTE(peer_m[r] + 16 + eb * 8);
            }
            // wait for this step's h (full barrier of buffer step&1)
            int b = step & 1;
            if (b) { SCAN_WAIT(mbar_base + 8, phF1); phF1 ^= 1; }
            else   { SCAN_WAIT(mbar_base + 0, phF0); phF0 ^= 1; }
        }

        // ---- dot: 4 gate rows of unit rb over 48 k-elems (packed f32x2) ----
        int par = step & 1;
        const float4* h4 = (const float4*)(h_pad + par * HPAD + ks * 52);
        u64 q0 = 0, q1 = 0, q2 = 0, q3 = 0;   // f32x2 accumulators (0.0f,0.0f)
        #pragma unroll
        for (int j = 0; j < 12; j++) {
            F4U hv; hv.f = h4[j];
            F4U v2; v2.f = Ws4[j * 384 + t];
            F4U v3; v3.f = Ws4[(12 + j) * 384 + t];
            FMA2(q0, wi[j].x, hv.u.x, q0); FMA2(q0, wi[j].y, hv.u.y, q0);
            FMA2(q1, wf[j].x, hv.u.x, q1); FMA2(q1, wf[j].y, hv.u.y, q1);
            FMA2(q2, v2.u.x, hv.u.x, q2);  FMA2(q2, v2.u.y, hv.u.y, q2);
            FMA2(q3, v3.u.x, hv.u.x, q3);  FMA2(q3, v3.u.y, hv.u.y, q3);
        }
        float a0, a1, a2, a3;
        { U64F2 z; z.u = q0; a0 = z.f.x + z.f.y; }
        { U64F2 z; z.u = q1; a1 = z.f.x + z.f.y; }
        { U64F2 z; z.u = q2; a2 = z.f.x + z.f.y; }
        { U64F2 z; z.u = q3; a3 = z.f.x + z.f.y; }

        // reduce over the 8 k-slices (lane bits 0..2)
        a0 += __shfl_xor_sync(0xffffffffu, a0, 1);
        a1 += __shfl_xor_sync(0xffffffffu, a1, 1);
        a2 += __shfl_xor_sync(0xffffffffu, a2, 1);
        a3 += __shfl_xor_sync(0xffffffffu, a3, 1);
        a0 += __shfl_xor_sync(0xffffffffu, a0, 2);
        a1 += __shfl_xor_sync(0xffffffffu, a1, 2);
        a2 += __shfl_xor_sync(0xffffffffu, a2, 2);
        a3 += __shfl_xor_sync(0xffffffffu, a3, 2);
        a0 += __shfl_xor_sync(0xffffffffu, a0, 4);
        a1 += __shfl_xor_sync(0xffffffffu, a1, 4);
        a2 += __shfl_xor_sync(0xffffffffu, a2, 4);
        a3 += __shfl_xor_sync(0xffffffffu, a3, 4);

        if (owner) {
            float gi = a0 + g0 + bh0;
            float gf = a1 + g1 + bh1;
            float gg = a2 + g2 + bh2;
            float go = a3 + g3 + bh3;
            c = sigm_fast(gf) * c + sigm_fast(gi) * tanh_fast(gg);
            float h = sigm_fast(go) * tanh_fast(c);
            lout[(size_t)step * HID] = h;

            if (step < len - 1) {
                int bw = (step + 1) & 1;
                // wait until every CTA finished reading buffer bw (step-1 dot)
                if (step >= 1) {
                    if (bw) { SCAN_WAIT(mbar_base + 24, phE1); phE1 ^= 1; }
                    else    { SCAN_WAIT(mbar_base + 16, phE0); phE0 ^= 1; }
                }
                // t0 re-arms the full barrier just consumed (next use = step+2)
                // BEFORE its own sends: remote senders to it causally depend on
                // t0's bytes below, so expect_tx precedes every complete_tx.
                if (t == 0 && step >= 1 && step <= len - 3)
                    SCAN_EXPECT_TX(mbar_base + (step & 1) * 8, 1536);
                // push h to all 8 CTAs' buffer bw with tx accounting
                uint32_t off = (uint32_t)(bw * HPAD + (int)rank * 52 + rb) * 4;
                uint32_t hb  = __float_as_uint(h);
                #pragma unroll
                for (int r = 0; r < 8; r++)
                    SCAN_ST_ASYNC(peer_h[r] + off, hb, peer_m[r] + bw * 8);
            }
        }
    }

    asm volatile("barrier.cluster.arrive.aligned;" ::: "memory");
    asm volatile("barrier.cluster.wait.aligned;" ::: "memory");
}

// ============================================================================
// launch — y1 GEMM forked onto a second stream (proven R11 pattern).
// ============================================================================
extern "C" void kernel_launch(void* const* d_in, const int* in_sizes, int n_in,
                              void* d_out, int out_size)
{
    const float* enc    = (const float*)d_in[0];
    const float* extra  = (const float*)d_in[1];
    const int*   forced = (const int*)  d_in[2];
    const int*   lens   = (const int*)  d_in[3];
    const float* emb    = (const float*)d_in[4];
    const float* initt  = (const float*)d_in[5];
    const float* W_ih   = (const float*)d_in[6];
    const float* W_hh   = (const float*)d_in[7];
    const float* b_ih   = (const float*)d_in[8];
    const float* b_hh   = (const float*)d_in[9];
    const float* wh1    = (const float*)d_in[10];
    const float* wh2    = (const float*)d_in[11];
    const float* wsig   = (const float*)d_in[12];

    float* out    = (float*)d_out;
    float* fusion = out;                               // [T,384]
    float* lstm   = out + (size_t)T_TOK * HID;         // [T,384]

    float *Xp, *gxp, *y1p, *x1p;
    cudaGetSymbolAddress((void**)&Xp,  g_X);
    cudaGetSymbolAddress((void**)&gxp, g_gx);
    cudaGetSymbolAddress((void**)&y1p, g_y1);
    cudaGetSymbolAddress((void**)&x1p, g_x1);

    cudaFuncSetAttribute(lstm_scan_kernel,
                         cudaFuncAttributeMaxDynamicSharedMemorySize,
                         SCAN_SMEM_BYTES);

    // side stream + fork/join events (created per call; never destroyed —
    // destroying capture-participating objects mid-capture is illegal, and
    // kernel_launch runs only a couple of times)
    cudaStream_t s2;
    cudaStreamCreateWithFlags(&s2, cudaStreamNonBlocking);
    cudaEvent_t evFork, evJoin;
    cudaEventCreateWithFlags(&evFork, cudaEventDisableTiming);
    cudaEventCreateWithFlags(&evJoin, cudaEventDisableTiming);

    // fork: s2 inherits the capture DAG from the main stream
    cudaEventRecord(evFork, 0);
    cudaStreamWaitEvent(s2, evFork, 0);

    // y1 = tanh(extra) @ wh2^T  — input-only dependency, overlaps everything
    sgemm_k<MODE_TANHA><<<dim3(HID / BN, T_TOK / BM), 256, 0, s2>>>(
        extra, nullptr, wh2, nullptr, y1p, nullptr, nullptr, HID, HID);
    cudaEventRecord(evJoin, s2);

    // main stream: 1) build X
    prepare_kernel<<<(T_TOK * 96 + 255) / 256, 256>>>(enc, forced, lens, emb, initt);

    // 2) gx = X @ W_ih^T + b_ih   [T,1536]
    sgemm_k<MODE_BIAS><<<dim3(NGATE / BN, T_TOK / BM), 256>>>(
        Xp, nullptr, W_ih, b_ih, gxp, nullptr, nullptr, NGATE, HID);

    // 3) LSTM scan -> lstm (second half of d_out); y1 runs on spare SMs
    lstm_scan_kernel<<<128, SCAN_THREADS, SCAN_SMEM_BYTES>>>(gxp, W_hh, b_hh, lens, lstm);

    // 4) x1 = tanh(lstm) @ wh1^T
    sgemm_k<MODE_TANHA><<<dim3(HID / BN, T_TOK / BM), 256>>>(
        lstm, nullptr, wh1, nullptr, x1p, nullptr, nullptr, HID, HID);

    // join: fusion consumes y1
    cudaStreamWaitEvent(0, evJoin, 0);

    // 5) f = sigmoid([x1|y1] @ Wsig^T); fusion epilogue -> first half of d_out
    sgemm_k<MODE_FUSION><<<dim3(HID / BN, T_TOK / BM), 256>>>(
        x1p, y1p, wsig, nullptr, fusion, lstm, extra, HID, 2 * HID);
}

// round 15
// speedup vs baseline: 1.1634x; 1.0620x over previous
#include <cuda_runtime.h>
#include <math.h>
#include <stdint.h>

// ---------------- problem constants (fixed by setup_inputs) ----------------
#define T_TOK 32768
#define HID   384
#define NGATE 1536
#define NSEQ  16

// ---------------- scratch (static device arrays; no allocation) ------------
__device__ float g_X [(size_t)T_TOK * HID];    // [T,384] LSTM input (enc|prev)
__device__ float g_gx[(size_t)T_TOK * NGATE];  // [T,1536] input gate preacts
__device__ float g_y1[(size_t)T_TOK * HID];    // tanh(extra)@wh2^T
__device__ float g_x1[(size_t)T_TOK * HID];    // tanh(lstm)@wh1^T

__device__ __forceinline__ float sigm(float x) { return 1.f / (1.f + expf(-x)); }

// fast MUFU-based pointwise for the scan (accuracy-preserving forms)
#define LOG2E 1.4426950408889634f
__device__ __forceinline__ float sigm_fast(float x)
{
    float e;
    asm("ex2.approx.f32 %0, %1;" : "=f"(e) : "f"(-x * LOG2E));
    float r;
    asm("rcp.approx.f32 %0, %1;" : "=f"(r) : "f"(1.f + e));
    return r;
}
__device__ __forceinline__ float tanh_fast(float x)
{
    // tanh(x) = 1 - 2/(1+e^{2x}); safe at both tails (no inf/inf)
    float e;
    asm("ex2.approx.f32 %0, %1;" : "=f"(e) : "f"(x * (2.f * LOG2E)));
    float r;
    asm("rcp.approx.f32 %0, %1;" : "=f"(r) : "f"(1.f + e));
    return 1.f - 2.f * r;
}

// ============================================================================
// prepare: build X = [encoded | prev_label_embedding]
// ============================================================================
__global__ void prepare_kernel(const float* __restrict__ enc,
                               const int*   __restrict__ forced,
                               const int*   __restrict__ lens,
                               const float* __restrict__ emb,
                               const float* __restrict__ initt)
{
    int idx = blockIdx.x * blockDim.x + threadIdx.x;   // T*96 float4 slots
    if (idx >= T_TOK * 96) return;
    int tok = idx / 96;
    int q   = idx - tok * 96;

    float4 v;
    if (q < 64) {
        v = ((const float4*)enc)[(size_t)tok * 64 + q];
    } else {
        bool is64 = (lens[1] == 0);        // int64 layout heuristic (len!=0 always)
        bool is_start = false;
        int srt = 0;
        #pragma unroll
        for (int i = 0; i < NSEQ; i++) {
            if (tok == srt) is_start = true;
            srt += lens[is64 ? 2 * i : i];
        }
        if (is_start) {
            v = ((const float4*)initt)[q - 64];
        } else {
            int fi = forced[is64 ? 2 * (tok - 1) : (tok - 1)];
            v = ((const float4*)(emb + (size_t)fi * 128))[q - 64];
        }
    }
    ((float4*)g_X)[(size_t)tok * 96 + q] = v;
}

// ============================================================================
// SGEMM (PROVEN R2 version): C = opA(A) @ B^T (+epilogue)
// BM=BN=128, BK=16, 256 threads, 8x8 micro-tile.
// ============================================================================
#define BM 128
#define BN 128
#define BK 16

#define MODE_BIAS   0
#define MODE_TANHA  1
#define MODE_FUSION 2

__device__ __forceinline__ float fuse_elem(float pre, float L, float Ev)
{
    float f  = 1.f / (1.f + expf(-pre));
    float x0 = tanhf(L);
    float y0 = tanhf(Ev);
    float x2 = f * x0 + L;
    float y2 = (1.f - f) * y0 + Ev;
    return f * x2 + (1.f - f) * y2;
}

template<int MODE>
__global__ __launch_bounds__(256)
void sgemm_k(const float* __restrict__ A, const float* __restrict__ A2,
             const float* __restrict__ B, const float* __restrict__ bias,
             float* __restrict__ C,
             const float* __restrict__ E1, const float* __restrict__ E2,
             int N, int K)
{
    __shared__ float As[BK][BM + 4];
    __shared__ float Bs[BK][BN + 4];

    int tid = threadIdx.x;
    int m0  = blockIdx.y * BM;
    int n0  = blockIdx.x * BN;
    int tx  = tid & 15;
    int ty  = tid >> 4;

    float acc[8][8];
    #pragma unroll
    for (int i = 0; i < 8; i++)
        #pragma unroll
        for (int j = 0; j < 8; j++) acc[i][j] = 0.f;

    for (int k0 = 0; k0 < K; k0 += BK) {
        #pragma unroll
        for (int i = 0; i < 2; i++) {
            int f  = tid + i * 256;
            int r  = f >> 2;
            int kq = f & 3;
            const float* src;
            if (MODE == MODE_FUSION) {
                src = (k0 < 384) ? (A  + (size_t)(m0 + r) * 384 + k0)
                                 : (A2 + (size_t)(m0 + r) * 384 + (k0 - 384));
            } else {
                src = A + (size_t)(m0 + r) * K + k0;
            }
            float4 v = *(const float4*)(src + kq * 4);
            if (MODE == MODE_TANHA) {
                v.x = tanhf(v.x); v.y = tanhf(v.y);
                v.z = tanhf(v.z); v.w = tanhf(v.w);
            }
            As[kq * 4 + 0][r] = v.x; As[kq * 4 + 1][r] = v.y;
            As[kq * 4 + 2][r] = v.z; As[kq * 4 + 3][r] = v.w;
        }
        #pragma unroll
        for (int i = 0; i < 2; i++) {
            int f  = tid + i * 256;
            int r  = f >> 2;
            int kq = f & 3;
            float4 v = *(const float4*)(B + (size_t)(n0 + r) * K + k0 + kq * 4);
            Bs[kq * 4 + 0][r] = v.x; Bs[kq * 4 + 1][r] = v.y;
            Bs[kq * 4 + 2][r] = v.z; Bs[kq * 4 + 3][r] = v.w;
        }
        __syncthreads();

        #pragma unroll
        for (int kk = 0; kk < BK; kk++) {
            float a[8], b[8];
            float4 a0 = *(const float4*)&As[kk][ty * 8];
            float4 a1 = *(const float4*)&As[kk][ty * 8 + 4];
            float4 b0 = *(const float4*)&Bs[kk][tx * 8];
            float4 b1 = *(const float4*)&Bs[kk][tx * 8 + 4];
            a[0]=a0.x; a[1]=a0.y; a[2]=a0.z; a[3]=a0.w;
            a[4]=a1.x; a[5]=a1.y; a[6]=a1.z; a[7]=a1.w;
            b[0]=b0.x; b[1]=b0.y; b[2]=b0.z; b[3]=b0.w;
            b[4]=b1.x; b[5]=b1.y; b[6]=b1.z; b[7]=b1.w;
            #pragma unroll
            for (int i = 0; i < 8; i++)
                #pragma unroll
                for (int j = 0; j < 8; j++)
                    acc[i][j] = fmaf(a[i], b[j], acc[i][j]);
        }
        __syncthreads();
    }

    #pragma unroll
    for (int i = 0; i < 8; i++) {
        size_t m = (size_t)(m0 + ty * 8 + i);
        #pragma unroll
        for (int q = 0; q < 2; q++) {
            int n = n0 + tx * 8 + q * 4;
            float r0 = acc[i][q * 4 + 0], r1 = acc[i][q * 4 + 1];
            float r2 = acc[i][q * 4 + 2], r3 = acc[i][q * 4 + 3];
            if (MODE == MODE_BIAS) {
                float4 bv = *(const float4*)(bias + n);
                r0 += bv.x; r1 += bv.y; r2 += bv.z; r3 += bv.w;
            }
            if (MODE == MODE_FUSION) {
                float4 L = *(const float4*)(E1 + m * 384 + n);
                float4 E = *(const float4*)(E2 + m * 384 + n);
                r0 = fuse_elem(r0, L.x, E.x); r1 = fuse_elem(r1, L.y, E.y);
                r2 = fuse_elem(r2, L.z, E.z); r3 = fuse_elem(r3, L.w, E.w);
            }
            float4 ov = make_float4(r0, r1, r2, r3);
            *(float4*)(C + m * N + n) = ov;
        }
    }
}

// ============================================================================
// LSTM scan v7: TRIPLE-buffered h exchange — the empty barriers (and their
// fabric round-trip) are deleted. Writes at step s+2 target the buffer read
// at step s; ordering comes from: our reads(b,s) -> syncthreads(s+1) ->
// our sends(s+1) -> remote full-wait(s+2) -> remote sends(s+2) overwrite b.
// Re-arm causality: t0 re-arms fb[s%3] right after its wait at step s,
// before its own send; remote sends targeting it (step s+2) causally follow
// our step-(s+1) sends, which follow the re-arm.
// Dot = packed f32x2; pointwise = MUFU fast forms (both proven in R14).
// ============================================================================
#define SCAN_THREADS 384
#define WS_FLOATS (24 * 384 * 4)     // 96 floats/thread of W in smem
#define HPAD 416                     // 8 chunks * 52 floats
#define NBUF 3
#define MBAR_OFF ((WS_FLOATS + NBUF * HPAD) * 4)
#define SCAN_SMEM_BYTES (MBAR_OFF + 32)

#define SCAN_MBAR_INIT(addr, cnt) \
    asm volatile("mbarrier.init.shared.b64 [%0], %1;" :: "r"(addr), "r"(cnt) : "memory")
#define SCAN_EXPECT_TX(addr, tx) \
    asm volatile("mbarrier.arrive.expect_tx.shared.b64 _, [%0], %1;" :: "r"(addr), "r"(tx) : "memory")
#define SCAN_ST_ASYNC(addr, val, mbar) \
    asm volatile("st.async.weak.shared::cluster.mbarrier::complete_tx::bytes.b32 [%0], %1, [%2];" \
                 :: "r"(addr), "r"(val), "r"(mbar) : "memory")
#define SCAN_WAIT(mbar, parity) do {                                           \
    uint32_t _done;                                                            \
    asm volatile("{\n\t.reg .pred p;\n\t"                                      \
      "mbarrier.try_wait.parity.acquire.cluster.shared::cta.b64 p, [%1], %2;\n\t" \
      "selp.b32 %0, 1, 0, p;\n\t}" : "=r"(_done) : "r"(mbar), "r"(parity) : "memory"); \
    while (!_done) {                                                           \
      asm volatile("{\n\t.reg .pred p;\n\t"                                    \
        "mbarrier.try_wait.parity.acquire.cluster.shared::cta.b64 p, [%1], %2, 0x989680;\n\t" \
        "selp.b32 %0, 1, 0, p;\n\t}" : "=r"(_done) : "r"(mbar), "r"(parity) : "memory"); \
    }                                                                          \
} while (0)

// packed f32x2 fma: d = a*b + c elementwise on 2 packed floats
#define FMA2(d, a, b, c) \
    asm("fma.rn.f32x2 %0, %1, %2, %3;" : "=l"(d) : "l"(a), "l"(b), "l"(c))

typedef unsigned long long u64;
union F4U {
    float4 f;
    ulonglong2 u;
};
union U64F2 {
    u64 u;
    float2 f;
};

__global__ void __cluster_dims__(8, 1, 1) __launch_bounds__(SCAN_THREADS, 1)
lstm_scan_kernel(const float* __restrict__ gx, const float* __restrict__ W_hh,
                 const float* __restrict__ b_hh, const int* __restrict__ lens,
                 float* __restrict__ lstm)
{
    extern __shared__ float sm[];
    float4* Ws4   = (float4*)sm;          // [24][384] float4 (gates g,o)
    float*  h_pad = sm + WS_FLOATS;       // [NBUF][HPAD]

    uint32_t smem_base;
    asm("{ .reg .u64 u; cvta.to.shared.u64 u, %1; cvt.u32.u64 %0, u; }"
        : "=r"(smem_base) : "l"(sm));
    uint32_t hpad_base = smem_base + WS_FLOATS * 4;
    uint32_t mbar_base = smem_base + MBAR_OFF;   // full0@0 full1@8 full2@16

    int t = threadIdx.x;
    uint32_t rank;
    asm("mov.u32 %0, %%cluster_ctarank;" : "=r"(rank));
    int seq = blockIdx.x >> 3;

    bool is64 = (lens[1] == 0);
    int start = 0;
    for (int i = 0; i < seq; i++) start += lens[is64 ? 2 * i : i];
    int len = lens[is64 ? 2 * seq : seq];

    int ks    = t & 7;        // k-slice: k in [ks*48, ks*48+48)
    int rb    = t >> 3;       // hidden unit (local 0..47)
    int kbase = ks * 48;
    bool owner = (ks == 0);

    // ---- stage W: gates i,f -> registers (as packed f32x2); g,o -> smem ----
    ulonglong2 wi[12], wf[12];
    #pragma unroll
    for (int g = 0; g < 4; g++) {
        int grow = g * HID + (int)rank * 48 + rb;
        const float4* src = (const float4*)(W_hh + (size_t)grow * HID + kbase);
        if (g == 0) {
            #pragma unroll
            for (int j = 0; j < 12; j++) { F4U v; v.f = src[j]; wi[j] = v.u; }
        } else if (g == 1) {
            #pragma unroll
            for (int j = 0; j < 12; j++) { F4U v; v.f = src[j]; wf[j] = v.u; }
        } else {
            #pragma unroll
            for (int j = 0; j < 12; j++) Ws4[((g - 2) * 12 + j) * 384 + t] = src[j];
        }
    }

    // ---- owner-lane state ----
    float c = 0.f, bh0 = 0.f, bh1 = 0.f, bh2 = 0.f, bh3 = 0.f;
    const float* gxp  = gx;
    float*       lout = lstm;
    if (owner) {
        int u = (int)rank * 48 + rb;
        bh0 = b_hh[u];            bh1 = b_hh[HID + u];
        bh2 = b_hh[2 * HID + u];  bh3 = b_hh[3 * HID + u];
        gxp  = gx   + (size_t)start * NGATE + u;
        lout = lstm + (size_t)start * HID   + u;
    }

    // ---- peer base addresses (h_pad and mbar block in each cluster CTA) ----
    uint32_t peer_h[8], peer_m[8];
    #pragma unroll
    for (int r = 0; r < 8; r++) {
        asm("mapa.shared::cluster.u32 %0, %1, %2;" : "=r"(peer_h[r]) : "r"(hpad_base), "r"(r));
        asm("mapa.shared::cluster.u32 %0, %1, %2;" : "=r"(peer_m[r]) : "r"(mbar_base), "r"(r));
    }

    // ---- init: mbars (3 fulls, pre-armed for their first use) + zero h ----
    if (t == 0) {
        SCAN_MBAR_INIT(mbar_base + 0, 1);     // full0 (first waited step 3)
        SCAN_MBAR_INIT(mbar_base + 8, 1);     // full1 (first waited step 1)
        SCAN_MBAR_INIT(mbar_base + 16, 1);    // full2 (first waited step 2)
        SCAN_EXPECT_TX(mbar_base + 0, 1536);
        SCAN_EXPECT_TX(mbar_base + 8, 1536);
        SCAN_EXPECT_TX(mbar_base + 16, 1536);
    }
    for (int i = t; i < NBUF * HPAD; i += SCAN_THREADS) h_pad[i] = 0.f;
    __syncthreads();
    asm volatile("barrier.cluster.arrive.aligned;" ::: "memory");
    asm volatile("barrier.cluster.wait.aligned;" ::: "memory");

    int ph0 = 0, ph1 = 0, ph2 = 0;
    int par = 0;                  // step % 3 (buffer read this step)

    for (int step = 0; step < len; step++) {
        // gx for this step (owner lanes) — issue before any waiting
        float g0 = 0.f, g1 = 0.f, g2 = 0.f, g3 = 0.f;
        if (owner) {
            const float* gp = gxp + (size_t)step * NGATE;
            g0 = __ldg(gp);
            g1 = __ldg(gp + HID);
            g2 = __ldg(gp + 2 * HID);
            g3 = __ldg(gp + 3 * HID);
        }
        // all local threads done with step-1 (orders our reads before our
        // sends this step -> closes the 3-step reuse hazard cluster-wide)
        __syncthreads();

        if (step > 0) {
            // wait for this step's h (full barrier of buffer par)
            if (par == 0)      { SCAN_WAIT(mbar_base + 0,  ph0); ph0 ^= 1; }
            else if (par == 1) { SCAN_WAIT(mbar_base + 8,  ph1); ph1 ^= 1; }
            else               { SCAN_WAIT(mbar_base + 16, ph2); ph2 ^= 1; }
            // t0 re-arms the barrier just consumed (next use = step+3);
            // precedes t0's own send below => precedes all remote sends
            // targeting it (they causally follow our step-(s+1) sends).
            if (t == 0 && step <= len - 4)
                SCAN_EXPECT_TX(mbar_base + par * 8, 1536);
        }

        // ---- dot: 4 gate rows of unit rb over 48 k-elems (packed f32x2) ----
        const float4* h4 = (const float4*)(h_pad + par * HPAD + ks * 52);
        u64 q0 = 0, q1 = 0, q2 = 0, q3 = 0;   // f32x2 accumulators (0.0f,0.0f)
        #pragma unroll
        for (int j = 0; j < 12; j++) {
            F4U hv; hv.f = h4[j];
            F4U v2; v2.f = Ws4[j * 384 + t];
            F4U v3; v3.f = Ws4[(12 + j) * 384 + t];
            FMA2(q0, wi[j].x, hv.u.x, q0); FMA2(q0, wi[j].y, hv.u.y, q0);
            FMA2(q1, wf[j].x, hv.u.x, q1); FMA2(q1, wf[j].y, hv.u.y, q1);
            FMA2(q2, v2.u.x, hv.u.x, q2);  FMA2(q2, v2.u.y, hv.u.y, q2);
            FMA2(q3, v3.u.x, hv.u.x, q3);  FMA2(q3, v3.u.y, hv.u.y, q3);
        }
        float a0, a1, a2, a3;
        { U64F2 z; z.u = q0; a0 = z.f.x + z.f.y; }
        { U64F2 z; z.u = q1; a1 = z.f.x + z.f.y; }
        { U64F2 z; z.u = q2; a2 = z.f.x + z.f.y; }
        { U64F2 z; z.u = q3; a3 = z.f.x + z.f.y; }

        // reduce over the 8 k-slices (lane bits 0..2)
        a0 += __shfl_xor_sync(0xffffffffu, a0, 1);
        a1 += __shfl_xor_sync(0xffffffffu, a1, 1);
        a2 += __shfl_xor_sync(0xffffffffu, a2, 1);
        a3 += __shfl_xor_sync(0xffffffffu, a3, 1);
        a0 += __shfl_xor_sync(0xffffffffu, a0, 2);
        a1 += __shfl_xor_sync(0xffffffffu, a1, 2);
        a2 += __shfl_xor_sync(0xffffffffu, a2, 2);
        a3 += __shfl_xor_sync(0xffffffffu, a3, 2);
        a0 += __shfl_xor_sync(0xffffffffu, a0, 4);
        a1 += __shfl_xor_sync(0xffffffffu, a1, 4);
        a2 += __shfl_xor_sync(0xffffffffu, a2, 4);
        a3 += __shfl_xor_sync(0xffffffffu, a3, 4);

        if (owner) {
            float gi = a0 + g0 + bh0;
            float gf = a1 + g1 + bh1;
            float gg = a2 + g2 + bh2;
            float go = a3 + g3 + bh3;
            c = sigm_fast(gf) * c + sigm_fast(gi) * tanh_fast(gg);
            float h = sigm_fast(go) * tanh_fast(c);
            lout[(size_t)step * HID] = h;

            if (step < len - 1) {
                int bb = par + 1; if (bb == NBUF) bb = 0;   // (step+1) % 3
                uint32_t off = (uint32_t)(bb * HPAD + (int)rank * 52 + rb) * 4;
                uint32_t hb  = __float_as_uint(h);
                #pragma unroll
                for (int r = 0; r < 8; r++)
                    SCAN_ST_ASYNC(peer_h[r] + off, hb, peer_m[r] + bb * 8);
            }
        }
        par = par + 1; if (par == NBUF) par = 0;
    }

    asm volatile("barrier.cluster.arrive.aligned;" ::: "memory");
    asm volatile("barrier.cluster.wait.aligned;" ::: "memory");
}

// ============================================================================
// launch — y1 GEMM forked onto a second stream (proven R11 pattern).
// ============================================================================
extern "C" void kernel_launch(void* const* d_in, const int* in_sizes, int n_in,
                              void* d_out, int out_size)
{
    const float* enc    = (const float*)d_in[0];
    const float* extra  = (const float*)d_in[1];
    const int*   forced = (const int*)  d_in[2];
    const int*   lens   = (const int*)  d_in[3];
    const float* emb    = (const float*)d_in[4];
    const float* initt  = (const float*)d_in[5];
    const float* W_ih   = (const float*)d_in[6];
    const float* W_hh   = (const float*)d_in[7];
    const float* b_ih   = (const float*)d_in[8];
    const float* b_hh   = (const float*)d_in[9];
    const float* wh1    = (const float*)d_in[10];
    const float* wh2    = (const float*)d_in[11];
    const float* wsig   = (const float*)d_in[12];

    float* out    = (float*)d_out;
    float* fusion = out;                               // [T,384]
    float* lstm   = out + (size_t)T_TOK * HID;         // [T,384]

    float *Xp, *gxp, *y1p, *x1p;
    cudaGetSymbolAddress((void**)&Xp,  g_X);
    cudaGetSymbolAddress((void**)&gxp, g_gx);
    cudaGetSymbolAddress((void**)&y1p, g_y1);
    cudaGetSymbolAddress((void**)&x1p, g_x1);

    cudaFuncSetAttribute(lstm_scan_kernel,
                         cudaFuncAttributeMaxDynamicSharedMemorySize,
                         SCAN_SMEM_BYTES);

    // side stream + fork/join events (created per call; never destroyed —
    // destroying capture-participating objects mid-capture is illegal, and
    // kernel_launch runs only a couple of times)
    cudaStream_t s2;
    cudaStreamCreateWithFlags(&s2, cudaStreamNonBlocking);
    cudaEvent_t evFork, evJoin;
    cudaEventCreateWithFlags(&evFork, cudaEventDisableTiming);
    cudaEventCreateWithFlags(&evJoin, cudaEventDisableTiming);

    // fork: s2 inherits the capture DAG from the main stream
    cudaEventRecord(evFork, 0);
    cudaStreamWaitEvent(s2, evFork, 0);

    // y1 = tanh(extra) @ wh2^T  — input-only dependency, overlaps everything
    sgemm_k<MODE_TANHA><<<dim3(HID / BN, T_TOK / BM), 256, 0, s2>>>(
        extra, nullptr, wh2, nullptr, y1p, nullptr, nullptr, HID, HID);
    cudaEventRecord(evJoin, s2);

    // main stream: 1) build X
    prepare_kernel<<<(T_TOK * 96 + 255) / 256, 256>>>(enc, forced, lens, emb, initt);

    // 2) gx = X @ W_ih^T + b_ih   [T,1536]
    sgemm_k<MODE_BIAS><<<dim3(NGATE / BN, T_TOK / BM), 256>>>(
        Xp, nullptr, W_ih, b_ih, gxp, nullptr, nullptr, NGATE, HID);

    // 3) LSTM scan -> lstm (second half of d_out); y1 runs on spare SMs
    lstm_scan_kernel<<<128, SCAN_THREADS, SCAN_SMEM_BYTES>>>(gxp, W_hh, b_hh, lens, lstm);

    // 4) x1 = tanh(lstm) @ wh1^T
    sgemm_k<MODE_TANHA><<<dim3(HID / BN, T_TOK / BM), 256>>>(
        lstm, nullptr, wh1, nullptr, x1p, nullptr, nullptr, HID, HID);

    // join: fusion consumes y1
    cudaStreamWaitEvent(0, evJoin, 0);

    // 5) f = sigmoid([x1|y1] @ Wsig^T); fusion epilogue -> first half of d_out
    sgemm_k<MODE_FUSION><<<dim3(HID / BN, T_TOK / BM), 256>>>(
        x1p, y1p, wsig, nullptr, fusion, lstm, extra, HID, 2 * HID);
}